// round 1
// baseline (speedup 1.0000x reference)
#include <cuda_runtime.h>
#include <math.h>

// Problem constants
#define B_   4
#define T_   2048
#define D_   1024
#define H_   16
#define DH_  64
#define NTOK (B_ * T_)          // 8192
#define QKV_COLS (3 * D_)       // 3072

// Scratch (allocation-free rule: __device__ globals)
__device__ float g_qkv[(size_t)NTOK * QKV_COLS];   // 96 MB
__device__ float g_attn[(size_t)NTOK * D_];        // 32 MB

// ---------------------------------------------------------------------------
// SGEMM:  C[M,N] = A[M,K] * Bw[N,K]^T + bias[N]
// A row-major [M,K], Bw row-major [N,K] (both K-contiguous -> NT gemm).
// BM=BN=128, BK=16, 256 threads, 8x8 per-thread tile.
// Requires M%128==0, N%128==0, K%16==0 (true for all uses here).
// ---------------------------------------------------------------------------
__global__ __launch_bounds__(256, 2)
void sgemm_nt_bias(const float* __restrict__ A, const float* __restrict__ Bw,
                   const float* __restrict__ bias, float* __restrict__ C,
                   int M, int N, int K)
{
    constexpr int BM = 128, BN = 128, BK = 16;
    __shared__ float As[BK][BM + 4];
    __shared__ float Bs[BK][BN + 4];

    const int tid = threadIdx.x;
    const int tr  = tid >> 4;          // 0..15  (row group)
    const int tc  = tid & 15;          // 0..15  (col group)
    const int row0 = blockIdx.y * BM;
    const int col0 = blockIdx.x * BN;

    const int lRow = tid >> 2;         // 0..63
    const int lCol = (tid & 3) << 2;   // 0,4,8,12

    float acc[8][8];
#pragma unroll
    for (int i = 0; i < 8; i++)
#pragma unroll
        for (int j = 0; j < 8; j++) acc[i][j] = 0.f;

    const float* Aptr = A  + (size_t)(row0 + lRow) * K + lCol;
    const float* Bptr = Bw + (size_t)(col0 + lRow) * K + lCol;

    for (int k0 = 0; k0 < K; k0 += BK) {
        // Load A tile (128 x 16), store transposed As[k][m]
#pragma unroll
        for (int r = 0; r < BM; r += 64) {
            float4 v = *(const float4*)(Aptr + (size_t)r * K + k0);
            As[lCol + 0][lRow + r] = v.x;
            As[lCol + 1][lRow + r] = v.y;
            As[lCol + 2][lRow + r] = v.z;
            As[lCol + 3][lRow + r] = v.w;
        }
        // Load B tile (128 x 16), store transposed Bs[k][n]
#pragma unroll
        for (int r = 0; r < BN; r += 64) {
            float4 v = *(const float4*)(Bptr + (size_t)r * K + k0);
            Bs[lCol + 0][lRow + r] = v.x;
            Bs[lCol + 1][lRow + r] = v.y;
            Bs[lCol + 2][lRow + r] = v.z;
            Bs[lCol + 3][lRow + r] = v.w;
        }
        __syncthreads();

#pragma unroll
        for (int kk = 0; kk < BK; kk++) {
            float a[8], b[8];
            *(float4*)&a[0] = *(const float4*)&As[kk][tr * 8];
            *(float4*)&a[4] = *(const float4*)&As[kk][tr * 8 + 4];
            *(float4*)&b[0] = *(const float4*)&Bs[kk][tc * 8];
            *(float4*)&b[4] = *(const float4*)&Bs[kk][tc * 8 + 4];
#pragma unroll
            for (int i = 0; i < 8; i++)
#pragma unroll
                for (int j = 0; j < 8; j++)
                    acc[i][j] += a[i] * b[j];
        }
        __syncthreads();
    }

    // Epilogue: add bias, vectorized store
#pragma unroll
    for (int i = 0; i < 8; i++) {
        const int row = row0 + tr * 8 + i;
#pragma unroll
        for (int j = 0; j < 8; j += 4) {
            const int col = col0 + tc * 8 + j;
            float4 o;
            o.x = acc[i][j + 0] + bias[col + 0];
            o.y = acc[i][j + 1] + bias[col + 1];
            o.z = acc[i][j + 2] + bias[col + 2];
            o.w = acc[i][j + 3] + bias[col + 3];
            *(float4*)&C[(size_t)row * N + col] = o;
        }
    }
}

// ---------------------------------------------------------------------------
// Flash attention, fp32, non-causal.
// Block: 256 threads = (ty 0..31) x (tx 0..7), handles 128 q-rows for one (b,h).
// k/v processed in 64-row tiles with online softmax.
// Smem layouts (all padded, transposed for vectorized conflict-free reads):
//   Qt[d][r]  64 x 132
//   Kt[d][c]  64 x 68
//   Vs[c][d]  64 x 68
//   Pt[c][r]  64 x 132
// Dynamic smem = 64*(132+68+68+132)*4 = 102400 bytes.
// ---------------------------------------------------------------------------
__global__ __launch_bounds__(256, 2)
void flash_attn_f32(const float* __restrict__ qkv, float* __restrict__ out)
{
    extern __shared__ float sm[];
    float* Qt = sm;                    // [64][132]
    float* Kt = Qt + 64 * 132;         // [64][68]
    float* Vs = Kt + 64 * 68;          // [64][68]
    float* Pt = Vs + 64 * 68;          // [64][132]

    const int tid = threadIdx.x;
    const int ty  = tid >> 3;          // 0..31 -> rows ty*4 .. ty*4+3
    const int tx  = tid & 7;           // 0..7  -> cols tx*8 .. tx*8+7
    const int bh  = blockIdx.y;
    const int b   = bh >> 4;
    const int h   = bh & 15;
    const int q0  = blockIdx.x * 128;
    const float scale = 0.125f;        // 1/sqrt(64)

    const float* qbase = qkv + (size_t)b * T_ * QKV_COLS + h * DH_;
    const float* kbase = qbase + D_;
    const float* vbase = qbase + 2 * D_;

    // ---- load Q tile transposed: Qt[d][r] ----
    {
        const int rr0 = tid >> 4;            // 0..15
        const int dc  = (tid & 15) << 2;     // 0,4,...,60
#pragma unroll
        for (int rr = rr0; rr < 128; rr += 16) {
            float4 v = *(const float4*)(qbase + (size_t)(q0 + rr) * QKV_COLS + dc);
            Qt[(dc + 0) * 132 + rr] = v.x;
            Qt[(dc + 1) * 132 + rr] = v.y;
            Qt[(dc + 2) * 132 + rr] = v.z;
            Qt[(dc + 3) * 132 + rr] = v.w;
        }
    }

    float m[4], l[4], acc[4][8];
#pragma unroll
    for (int i = 0; i < 4; i++) {
        m[i] = -INFINITY;
        l[i] = 0.f;
#pragma unroll
        for (int j = 0; j < 8; j++) acc[i][j] = 0.f;
    }

    for (int kt = 0; kt < T_ / 64; kt++) {
        __syncthreads();   // protect Kt/Vs/Pt reuse from previous iteration

        // ---- load K (transposed) and V tiles ----
        {
            const int cc0 = tid >> 4;
            const int dc  = (tid & 15) << 2;
#pragma unroll
            for (int cc = cc0; cc < 64; cc += 16) {
                const size_t roff = (size_t)(kt * 64 + cc) * QKV_COLS + dc;
                float4 kv4 = *(const float4*)(kbase + roff);
                Kt[(dc + 0) * 68 + cc] = kv4.x;
                Kt[(dc + 1) * 68 + cc] = kv4.y;
                Kt[(dc + 2) * 68 + cc] = kv4.z;
                Kt[(dc + 3) * 68 + cc] = kv4.w;
                float4 vv4 = *(const float4*)(vbase + roff);
                *(float4*)&Vs[cc * 68 + dc] = vv4;
            }
        }
        __syncthreads();

        // ---- S = Q K^T (raw dot, scaled later) ----
        float s[4][8];
#pragma unroll
        for (int i = 0; i < 4; i++)
#pragma unroll
            for (int j = 0; j < 8; j++) s[i][j] = 0.f;

#pragma unroll 4
        for (int d = 0; d < 64; d++) {
            float4 q4 = *(const float4*)&Qt[d * 132 + ty * 4];
            float4 k0 = *(const float4*)&Kt[d * 68 + tx * 8];
            float4 k1 = *(const float4*)&Kt[d * 68 + tx * 8 + 4];
            const float qq[4] = {q4.x, q4.y, q4.z, q4.w};
            const float kk[8] = {k0.x, k0.y, k0.z, k0.w, k1.x, k1.y, k1.z, k1.w};
#pragma unroll
            for (int i = 0; i < 4; i++)
#pragma unroll
                for (int j = 0; j < 8; j++)
                    s[i][j] += qq[i] * kk[j];
        }

        // ---- online softmax update ----
#pragma unroll
        for (int i = 0; i < 4; i++) {
            float rm = s[i][0];
#pragma unroll
            for (int j = 1; j < 8; j++) rm = fmaxf(rm, s[i][j]);
#pragma unroll
            for (int o = 1; o < 8; o <<= 1)
                rm = fmaxf(rm, __shfl_xor_sync(0xffffffffu, rm, o));
            const float mt = fmaxf(m[i], rm * scale);
            const float alpha = __expf(m[i] - mt);
            l[i] *= alpha;
#pragma unroll
            for (int j = 0; j < 8; j++) acc[i][j] *= alpha;

            float rs = 0.f;
#pragma unroll
            for (int j = 0; j < 8; j++) {
                const float p = __expf(s[i][j] * scale - mt);
                s[i][j] = p;
                rs += p;
            }
#pragma unroll
            for (int o = 1; o < 8; o <<= 1)
                rs += __shfl_xor_sync(0xffffffffu, rs, o);
            l[i] += rs;
            m[i] = mt;
        }

        // ---- store P transposed: Pt[c][r] ----
#pragma unroll
        for (int j = 0; j < 8; j++)
#pragma unroll
            for (int i = 0; i < 4; i++)
                Pt[(tx * 8 + j) * 132 + ty * 4 + i] = s[i][j];
        __syncthreads();

        // ---- O += P V ----
#pragma unroll 4
        for (int c = 0; c < 64; c++) {
            float4 p4 = *(const float4*)&Pt[c * 132 + ty * 4];
            float4 v0 = *(const float4*)&Vs[c * 68 + tx * 8];
            float4 v1 = *(const float4*)&Vs[c * 68 + tx * 8 + 4];
            const float pp[4] = {p4.x, p4.y, p4.z, p4.w};
            const float vv[8] = {v0.x, v0.y, v0.z, v0.w, v1.x, v1.y, v1.z, v1.w};
#pragma unroll
            for (int i = 0; i < 4; i++)
#pragma unroll
                for (int j = 0; j < 8; j++)
                    acc[i][j] += pp[i] * vv[j];
        }
    }

    // ---- epilogue: normalize and write [tok, h*64+d] ----
#pragma unroll
    for (int i = 0; i < 4; i++) {
        const float inv = 1.f / l[i];
        const int row = q0 + ty * 4 + i;
        float* obase = out + (size_t)(b * T_ + row) * D_ + h * DH_ + tx * 8;
        float4 o0, o1;
        o0.x = acc[i][0] * inv; o0.y = acc[i][1] * inv;
        o0.z = acc[i][2] * inv; o0.w = acc[i][3] * inv;
        o1.x = acc[i][4] * inv; o1.y = acc[i][5] * inv;
        o1.z = acc[i][6] * inv; o1.w = acc[i][7] * inv;
        *(float4*)obase       = o0;
        *(float4*)(obase + 4) = o1;
    }
}

// ---------------------------------------------------------------------------
// kernel_launch
// Inputs (metadata order): x[B,T,D] f32, w_qkv[3D,D] f32, b_qkv[3D] f32,
//                          w_out[D,D] f32, b_out[D] f32
// Output: [B,T,D] f32
// ---------------------------------------------------------------------------
extern "C" void kernel_launch(void* const* d_in, const int* in_sizes, int n_in,
                              void* d_out, int out_size)
{
    const float* x     = (const float*)d_in[0];
    const float* w_qkv = (const float*)d_in[1];
    const float* b_qkv = (const float*)d_in[2];
    const float* w_out = (const float*)d_in[3];
    const float* b_out = (const float*)d_in[4];
    float* out = (float*)d_out;

    float* qkv_ptr = nullptr;
    float* attn_ptr = nullptr;
    cudaGetSymbolAddress((void**)&qkv_ptr, g_qkv);
    cudaGetSymbolAddress((void**)&attn_ptr, g_attn);

    // 1) QKV projection: [8192,3072] = x[8192,1024] @ w_qkv^T + b_qkv
    {
        dim3 grid(QKV_COLS / 128, NTOK / 128);
        sgemm_nt_bias<<<grid, 256>>>(x, w_qkv, b_qkv, qkv_ptr, NTOK, QKV_COLS, D_);
    }

    // 2) Flash attention -> g_attn in [tok, h*DH+d] layout
    {
        const int smem = 64 * (132 + 68 + 68 + 132) * (int)sizeof(float); // 102400
        cudaFuncSetAttribute(flash_attn_f32,
                             cudaFuncAttributeMaxDynamicSharedMemorySize, smem);
        dim3 grid(T_ / 128, B_ * H_);
        flash_attn_f32<<<grid, 256, smem>>>(qkv_ptr, attn_ptr);
    }

    // 3) Output projection: [8192,1024] = attn @ w_out^T + b_out
    {
        dim3 grid(D_ / 128, NTOK / 128);
        sgemm_nt_bias<<<grid, 256>>>(attn_ptr, w_out, b_out, out, NTOK, D_, D_);
    }
}

// round 2
// speedup vs baseline: 3.0461x; 3.0461x over previous
#include <cuda_runtime.h>
#include <cuda_bf16.h>
#include <math.h>
#include <stdint.h>

#define B_   4
#define T_   2048
#define D_   1024
#define H_   16
#define DH_  64
#define NTOK (B_ * T_)          // 8192
#define QKV_COLS (3 * D_)       // 3072

// Scratch (allocation-free rule: __device__ globals)
__device__ float g_qkv[(size_t)NTOK * QKV_COLS];   // 96 MB
__device__ float g_attn[(size_t)NTOK * D_];        // 32 MB

// ---------------------------------------------------------------------------
// helpers
// ---------------------------------------------------------------------------
__device__ __forceinline__ uint32_t su32(const void* p) {
    return (uint32_t)__cvta_generic_to_shared(p);
}
__device__ __forceinline__ void ldsm4(uint32_t* r, uint32_t a) {
    asm volatile("ldmatrix.sync.aligned.m8n8.x4.shared.b16 {%0,%1,%2,%3}, [%4];"
        : "=r"(r[0]), "=r"(r[1]), "=r"(r[2]), "=r"(r[3]) : "r"(a));
}
__device__ __forceinline__ void ldsm4t(uint32_t* r, uint32_t a) {
    asm volatile("ldmatrix.sync.aligned.m8n8.x4.trans.shared.b16 {%0,%1,%2,%3}, [%4];"
        : "=r"(r[0]), "=r"(r[1]), "=r"(r[2]), "=r"(r[3]) : "r"(a));
}
__device__ __forceinline__ void mma16816(float* c, const uint32_t* a,
                                         uint32_t b0, uint32_t b1) {
    asm volatile(
        "mma.sync.aligned.m16n8k16.row.col.f32.bf16.bf16.f32 "
        "{%0,%1,%2,%3},{%4,%5,%6,%7},{%8,%9},{%0,%1,%2,%3};"
        : "+f"(c[0]), "+f"(c[1]), "+f"(c[2]), "+f"(c[3])
        : "r"(a[0]), "r"(a[1]), "r"(a[2]), "r"(a[3]), "r"(b0), "r"(b1));
}
__device__ __forceinline__ uint32_t pkbf(float x, float y) {
    __nv_bfloat162 t = __floats2bfloat162_rn(x, y);
    return *reinterpret_cast<uint32_t*>(&t);
}
// split pair of floats into (hi, lo) packed bf16x2, x in low half
__device__ __forceinline__ void split2(float x, float y, uint32_t& hi, uint32_t& lo) {
    float hx = __bfloat162float(__float2bfloat16_rn(x));
    float hy = __bfloat162float(__float2bfloat16_rn(y));
    hi = pkbf(hx, hy);
    lo = pkbf(x - hx, y - hy);
}

// ---------------------------------------------------------------------------
// Split-bf16 tensor-core GEMM: C[M,N] = A[M,K] * Bw[N,K]^T + bias[N]
// BM=BN=128, BK=32, 256 threads (8 warps: 4(M) x 2(N), warp tile 32x64).
// 3-term split: Ahi*Bhi + Ahi*Blo + Alo*Bhi.
// ---------------------------------------------------------------------------
#define GST 40   // smem row stride in bf16 elems (32 + 8 pad)

__global__ __launch_bounds__(256, 2)
void gemm_bf16s(const float* __restrict__ A, const float* __restrict__ Bw,
                const float* __restrict__ bias, float* __restrict__ C,
                int M, int N, int K)
{
    __shared__ __nv_bfloat16 Ah[128 * GST], Al[128 * GST];
    __shared__ __nv_bfloat16 Bh[128 * GST], Bl[128 * GST];

    const int tid = threadIdx.x, lane = tid & 31, wid = tid >> 5;
    const int wm = wid & 3, wn = wid >> 2;
    const int row0 = blockIdx.y * 128, col0 = blockIdx.x * 128;

    float acc[2][8][4];
#pragma unroll
    for (int mt = 0; mt < 2; mt++)
#pragma unroll
        for (int nt = 0; nt < 8; nt++)
#pragma unroll
            for (int i = 0; i < 4; i++) acc[mt][nt][i] = 0.f;

    const int rbase = tid >> 3;          // 0..31
    const int cc    = (tid & 7) << 2;    // 0,4,...,28
    const float* Abase = A  + (size_t)row0 * K + cc;
    const float* Bbase = Bw + (size_t)col0 * K + cc;

    for (int k0 = 0; k0 < K; k0 += 32) {
        float4 av[4], bv[4];
#pragma unroll
        for (int t = 0; t < 4; t++) {
            av[t] = *(const float4*)(Abase + (size_t)(rbase + 32 * t) * K + k0);
            bv[t] = *(const float4*)(Bbase + (size_t)(rbase + 32 * t) * K + k0);
        }
        if (k0) __syncthreads();
#pragma unroll
        for (int t = 0; t < 4; t++) {
            const int r = rbase + 32 * t;
            uint32_t h0, l0, h1, l1;
            split2(av[t].x, av[t].y, h0, l0); split2(av[t].z, av[t].w, h1, l1);
            *(uint2*)&Ah[r * GST + cc] = make_uint2(h0, h1);
            *(uint2*)&Al[r * GST + cc] = make_uint2(l0, l1);
            split2(bv[t].x, bv[t].y, h0, l0); split2(bv[t].z, bv[t].w, h1, l1);
            *(uint2*)&Bh[r * GST + cc] = make_uint2(h0, h1);
            *(uint2*)&Bl[r * GST + cc] = make_uint2(l0, l1);
        }
        __syncthreads();

#pragma unroll
        for (int kk = 0; kk < 32; kk += 16) {
            uint32_t ah[2][4], al[2][4];
            const int cl = kk + ((lane >> 4) << 3);
#pragma unroll
            for (int mt = 0; mt < 2; mt++) {
                const int rw = wm * 32 + mt * 16 + (lane & 15);
                ldsm4(ah[mt], su32(&Ah[rw * GST + cl]));
                ldsm4(al[mt], su32(&Al[rw * GST + cl]));
            }
#pragma unroll
            for (int np = 0; np < 4; np++) {
                uint32_t bh[4], bl[4];
                const int rw = wn * 64 + np * 16 + (lane & 15);
                ldsm4(bh, su32(&Bh[rw * GST + cl]));
                ldsm4(bl, su32(&Bl[rw * GST + cl]));
#pragma unroll
                for (int mt = 0; mt < 2; mt++) {
#pragma unroll
                    for (int sub = 0; sub < 2; sub++) {
                        float* c = acc[mt][np * 2 + sub];
                        mma16816(c, ah[mt], bh[sub], bh[sub + 2]);
                        mma16816(c, ah[mt], bl[sub], bl[sub + 2]);
                        mma16816(c, al[mt], bh[sub], bh[sub + 2]);
                    }
                }
            }
        }
    }

    // epilogue
    const int g = lane >> 2, tq = lane & 3;
#pragma unroll
    for (int mt = 0; mt < 2; mt++) {
        const int r = row0 + wm * 32 + mt * 16 + g;
#pragma unroll
        for (int nt = 0; nt < 8; nt++) {
            const int c = col0 + wn * 64 + nt * 8 + tq * 2;
            float2 bi = *(const float2*)(bias + c);
            float2 v0 = make_float2(acc[mt][nt][0] + bi.x, acc[mt][nt][1] + bi.y);
            float2 v1 = make_float2(acc[mt][nt][2] + bi.x, acc[mt][nt][3] + bi.y);
            *(float2*)(C + (size_t)r * N + c)       = v0;
            *(float2*)(C + (size_t)(r + 8) * N + c) = v1;
        }
    }
}

// ---------------------------------------------------------------------------
// Flash attention with split-bf16 tensor cores.
// Block: 256 threads (8 warps), 128 q-rows per block, one (b,h).
// Warp owns 16 q-rows x full 128-col k-tile; Q frags register-resident;
// P stays in registers (S C-frag == PV A-frag layout); V via ldmatrix.trans.
// smem: Kh,Kl,Vh,Vl each [128][72] bf16 = 72 KB dynamic.
// ---------------------------------------------------------------------------
#define AST 72   // smem row stride (64 + 8 pad)

__global__ __launch_bounds__(256)
void attn_bf16s(const float* __restrict__ qkv, float* __restrict__ out)
{
    extern __shared__ __nv_bfloat16 smA[];
    __nv_bfloat16* Kh = smA;
    __nv_bfloat16* Kl = Kh + 128 * AST;
    __nv_bfloat16* Vh = Kl + 128 * AST;
    __nv_bfloat16* Vl = Vh + 128 * AST;

    const int tid = threadIdx.x, lane = tid & 31, wid = tid >> 5;
    const int b = blockIdx.y >> 4, h = blockIdx.y & 15;
    const int q0 = blockIdx.x * 128;
    const float scale = 0.125f;   // 1/sqrt(64)

    const float* qb = qkv + (size_t)b * T_ * QKV_COLS + h * DH_;
    const float* kb = qb + D_;
    const float* vb = qb + 2 * D_;

    const int rbase = tid >> 4;          // 0..15
    const int cc    = (tid & 15) << 2;   // 0,4,...,60

    // ---- stage Q into Kh/Kl, pull fragments into registers ----
#pragma unroll
    for (int t = 0; t < 8; t++) {
        const int r = rbase + t * 16;
        float4 v = *(const float4*)(qb + (size_t)(q0 + r) * QKV_COLS + cc);
        uint32_t h0, l0, h1, l1;
        split2(v.x, v.y, h0, l0); split2(v.z, v.w, h1, l1);
        *(uint2*)&Kh[r * AST + cc] = make_uint2(h0, h1);
        *(uint2*)&Kl[r * AST + cc] = make_uint2(l0, l1);
    }
    __syncthreads();
    uint32_t qh[4][4], ql[4][4];
#pragma unroll
    for (int kc = 0; kc < 4; kc++) {
        const int rw = wid * 16 + (lane & 15);
        const int cl = kc * 16 + ((lane >> 4) << 3);
        ldsm4(qh[kc], su32(&Kh[rw * AST + cl]));
        ldsm4(ql[kc], su32(&Kl[rw * AST + cl]));
    }
    __syncthreads();

    float oacc[8][4];
#pragma unroll
    for (int nt = 0; nt < 8; nt++)
#pragma unroll
        for (int i = 0; i < 4; i++) oacc[nt][i] = 0.f;
    float mr0 = -INFINITY, mr1 = -INFINITY, lr0 = 0.f, lr1 = 0.f;

    for (int kt = 0; kt < 16; kt++) {
        // ---- load + split-convert K,V tile ----
        float4 kv4[8], vv4[8];
#pragma unroll
        for (int t = 0; t < 8; t++) {
            const size_t roff = (size_t)(kt * 128 + rbase + t * 16) * QKV_COLS + cc;
            kv4[t] = *(const float4*)(kb + roff);
            vv4[t] = *(const float4*)(vb + roff);
        }
#pragma unroll
        for (int t = 0; t < 8; t++) {
            const int r = rbase + t * 16;
            uint32_t h0, l0, h1, l1;
            split2(kv4[t].x, kv4[t].y, h0, l0); split2(kv4[t].z, kv4[t].w, h1, l1);
            *(uint2*)&Kh[r * AST + cc] = make_uint2(h0, h1);
            *(uint2*)&Kl[r * AST + cc] = make_uint2(l0, l1);
            split2(vv4[t].x, vv4[t].y, h0, l0); split2(vv4[t].z, vv4[t].w, h1, l1);
            *(uint2*)&Vh[r * AST + cc] = make_uint2(h0, h1);
            *(uint2*)&Vl[r * AST + cc] = make_uint2(l0, l1);
        }
        __syncthreads();

        // ---- S = Q K^T  (16 n-tiles of 8 cols) ----
        float sacc[16][4];
#pragma unroll
        for (int nt = 0; nt < 16; nt++)
#pragma unroll
            for (int i = 0; i < 4; i++) sacc[nt][i] = 0.f;

#pragma unroll
        for (int np = 0; np < 8; np++) {
#pragma unroll
            for (int kc = 0; kc < 4; kc++) {
                uint32_t bh[4], bl[4];
                const int rw = np * 16 + (lane & 15);
                const int cl = kc * 16 + ((lane >> 4) << 3);
                ldsm4(bh, su32(&Kh[rw * AST + cl]));
                ldsm4(bl, su32(&Kl[rw * AST + cl]));
                mma16816(sacc[np * 2],     qh[kc], bh[0], bh[2]);
                mma16816(sacc[np * 2],     qh[kc], bl[0], bl[2]);
                mma16816(sacc[np * 2],     ql[kc], bh[0], bh[2]);
                mma16816(sacc[np * 2 + 1], qh[kc], bh[1], bh[3]);
                mma16816(sacc[np * 2 + 1], qh[kc], bl[1], bl[3]);
                mma16816(sacc[np * 2 + 1], ql[kc], bh[1], bh[3]);
            }
        }

        // ---- online softmax (row slot0 = regs 0,1; slot1 = regs 2,3) ----
        float tm0 = -INFINITY, tm1 = -INFINITY;
#pragma unroll
        for (int nt = 0; nt < 16; nt++) {
            tm0 = fmaxf(tm0, fmaxf(sacc[nt][0], sacc[nt][1]));
            tm1 = fmaxf(tm1, fmaxf(sacc[nt][2], sacc[nt][3]));
        }
        tm0 = fmaxf(tm0, __shfl_xor_sync(0xffffffffu, tm0, 1));
        tm0 = fmaxf(tm0, __shfl_xor_sync(0xffffffffu, tm0, 2));
        tm1 = fmaxf(tm1, __shfl_xor_sync(0xffffffffu, tm1, 1));
        tm1 = fmaxf(tm1, __shfl_xor_sync(0xffffffffu, tm1, 2));

        const float nm0 = fmaxf(mr0, tm0 * scale);
        const float nm1 = fmaxf(mr1, tm1 * scale);
        const float al0 = __expf(mr0 - nm0);
        const float al1 = __expf(mr1 - nm1);
        mr0 = nm0; mr1 = nm1;
#pragma unroll
        for (int nt = 0; nt < 8; nt++) {
            oacc[nt][0] *= al0; oacc[nt][1] *= al0;
            oacc[nt][2] *= al1; oacc[nt][3] *= al1;
        }

        float rs0 = 0.f, rs1 = 0.f;
        uint32_t ph[8][4], pl[8][4];
#pragma unroll
        for (int j = 0; j < 8; j++) {
            const float p00 = __expf(fmaf(sacc[2 * j][0],     scale, -nm0));
            const float p01 = __expf(fmaf(sacc[2 * j][1],     scale, -nm0));
            const float p10 = __expf(fmaf(sacc[2 * j][2],     scale, -nm1));
            const float p11 = __expf(fmaf(sacc[2 * j][3],     scale, -nm1));
            const float r00 = __expf(fmaf(sacc[2 * j + 1][0], scale, -nm0));
            const float r01 = __expf(fmaf(sacc[2 * j + 1][1], scale, -nm0));
            const float r10 = __expf(fmaf(sacc[2 * j + 1][2], scale, -nm1));
            const float r11 = __expf(fmaf(sacc[2 * j + 1][3], scale, -nm1));
            rs0 += (p00 + p01) + (r00 + r01);
            rs1 += (p10 + p11) + (r10 + r11);
            split2(p00, p01, ph[j][0], pl[j][0]);
            split2(p10, p11, ph[j][1], pl[j][1]);
            split2(r00, r01, ph[j][2], pl[j][2]);
            split2(r10, r11, ph[j][3], pl[j][3]);
        }
        rs0 += __shfl_xor_sync(0xffffffffu, rs0, 1);
        rs0 += __shfl_xor_sync(0xffffffffu, rs0, 2);
        rs1 += __shfl_xor_sync(0xffffffffu, rs1, 1);
        rs1 += __shfl_xor_sync(0xffffffffu, rs1, 2);
        lr0 = lr0 * al0 + rs0;
        lr1 = lr1 * al1 + rs1;

        // ---- O += P V  (8 k16 chunks; V via ldmatrix.trans) ----
#pragma unroll
        for (int j = 0; j < 8; j++) {
#pragma unroll
            for (int dp = 0; dp < 4; dp++) {
                uint32_t vhf[4], vlf[4];
                const int rw = j * 16 + (lane & 7) + ((lane >> 3) & 1) * 8;
                const int cl = dp * 16 + ((lane >> 4) << 3);
                ldsm4t(vhf, su32(&Vh[rw * AST + cl]));
                ldsm4t(vlf, su32(&Vl[rw * AST + cl]));
                mma16816(oacc[dp * 2],     ph[j], vhf[0], vhf[1]);
                mma16816(oacc[dp * 2],     ph[j], vlf[0], vlf[1]);
                mma16816(oacc[dp * 2],     pl[j], vhf[0], vhf[1]);
                mma16816(oacc[dp * 2 + 1], ph[j], vhf[2], vhf[3]);
                mma16816(oacc[dp * 2 + 1], ph[j], vlf[2], vlf[3]);
                mma16816(oacc[dp * 2 + 1], pl[j], vhf[2], vhf[3]);
            }
        }
        __syncthreads();
    }

    // ---- epilogue ----
    const float inv0 = 1.f / lr0, inv1 = 1.f / lr1;
    const int g = lane >> 2, tq = lane & 3;
    const size_t rowb = (size_t)(b * T_ + q0 + wid * 16 + g);
    float* o0 = out + rowb * D_ + h * DH_ + tq * 2;
    float* o1 = out + (rowb + 8) * D_ + h * DH_ + tq * 2;
#pragma unroll
    for (int nt = 0; nt < 8; nt++) {
        *(float2*)(o0 + nt * 8) = make_float2(oacc[nt][0] * inv0, oacc[nt][1] * inv0);
        *(float2*)(o1 + nt * 8) = make_float2(oacc[nt][2] * inv1, oacc[nt][3] * inv1);
    }
}

// ---------------------------------------------------------------------------
// kernel_launch
// ---------------------------------------------------------------------------
extern "C" void kernel_launch(void* const* d_in, const int* in_sizes, int n_in,
                              void* d_out, int out_size)
{
    const float* x     = (const float*)d_in[0];
    const float* w_qkv = (const float*)d_in[1];
    const float* b_qkv = (const float*)d_in[2];
    const float* w_out = (const float*)d_in[3];
    const float* b_out = (const float*)d_in[4];
    float* out = (float*)d_out;

    float* qkv_ptr = nullptr;
    float* attn_ptr = nullptr;
    cudaGetSymbolAddress((void**)&qkv_ptr, g_qkv);
    cudaGetSymbolAddress((void**)&attn_ptr, g_attn);

    // 1) QKV projection: [8192,3072] = x @ w_qkv^T + b_qkv
    {
        dim3 grid(QKV_COLS / 128, NTOK / 128);
        gemm_bf16s<<<grid, 256>>>(x, w_qkv, b_qkv, qkv_ptr, NTOK, QKV_COLS, D_);
    }

    // 2) Flash attention -> g_attn in [tok, h*DH+d] layout
    {
        const int smem = 4 * 128 * AST * (int)sizeof(__nv_bfloat16); // 73728
        cudaFuncSetAttribute(attn_bf16s,
                             cudaFuncAttributeMaxDynamicSharedMemorySize, smem);
        dim3 grid(T_ / 128, B_ * H_);
        attn_bf16s<<<grid, 256, smem>>>(qkv_ptr, attn_ptr);
    }

    // 3) Output projection: [8192,1024] = attn @ w_out^T + b_out
    {
        dim3 grid(D_ / 128, NTOK / 128);
        gemm_bf16s<<<grid, 256>>>(attn_ptr, w_out, b_out, out, NTOK, D_, D_);
    }
}

// round 4
// speedup vs baseline: 3.0712x; 1.0082x over previous
#include <cuda_runtime.h>
#include <cuda_bf16.h>
#include <math.h>
#include <stdint.h>

#define B_   4
#define T_   2048
#define D_   1024
#define H_   16
#define DH_  64
#define NTOK (B_ * T_)          // 8192
#define QKV_COLS (3 * D_)       // 3072

// ---------------------------------------------------------------------------
// split-bf16 global scratch (allocation-free rule: __device__ globals)
// ---------------------------------------------------------------------------
__device__ __nv_bfloat16 g_x_h[(size_t)NTOK * D_],        g_x_l[(size_t)NTOK * D_];
__device__ __nv_bfloat16 g_wqkv_h[(size_t)QKV_COLS * D_], g_wqkv_l[(size_t)QKV_COLS * D_];
__device__ __nv_bfloat16 g_wout_h[(size_t)D_ * D_],       g_wout_l[(size_t)D_ * D_];
__device__ __nv_bfloat16 g_qkv_h[(size_t)NTOK * QKV_COLS], g_qkv_l[(size_t)NTOK * QKV_COLS];
__device__ __nv_bfloat16 g_attn_h[(size_t)NTOK * D_],     g_attn_l[(size_t)NTOK * D_];

// ---------------------------------------------------------------------------
// helpers
// ---------------------------------------------------------------------------
__device__ __forceinline__ uint32_t su32(const void* p) {
    return (uint32_t)__cvta_generic_to_shared(p);
}
__device__ __forceinline__ void ldsm4(uint32_t* r, uint32_t a) {
    asm volatile("ldmatrix.sync.aligned.m8n8.x4.shared.b16 {%0,%1,%2,%3}, [%4];"
        : "=r"(r[0]), "=r"(r[1]), "=r"(r[2]), "=r"(r[3]) : "r"(a));
}
__device__ __forceinline__ void ldsm4t(uint32_t* r, uint32_t a) {
    asm volatile("ldmatrix.sync.aligned.m8n8.x4.trans.shared.b16 {%0,%1,%2,%3}, [%4];"
        : "=r"(r[0]), "=r"(r[1]), "=r"(r[2]), "=r"(r[3]) : "r"(a));
}
__device__ __forceinline__ void mma16816(float* c, const uint32_t* a,
                                         uint32_t b0, uint32_t b1) {
    asm volatile(
        "mma.sync.aligned.m16n8k16.row.col.f32.bf16.bf16.f32 "
        "{%0,%1,%2,%3},{%4,%5,%6,%7},{%8,%9},{%0,%1,%2,%3};"
        : "+f"(c[0]), "+f"(c[1]), "+f"(c[2]), "+f"(c[3])
        : "r"(a[0]), "r"(a[1]), "r"(a[2]), "r"(a[3]), "r"(b0), "r"(b1));
}
__device__ __forceinline__ uint32_t pkbf(float x, float y) {
    __nv_bfloat162 t = __floats2bfloat162_rn(x, y);
    return *reinterpret_cast<uint32_t*>(&t);
}
__device__ __forceinline__ void split2(float x, float y, uint32_t& hi, uint32_t& lo) {
    float hx = __bfloat162float(__float2bfloat16_rn(x));
    float hy = __bfloat162float(__float2bfloat16_rn(y));
    hi = pkbf(hx, hy);
    lo = pkbf(x - hx, y - hy);
}
__device__ __forceinline__ void cpa16(uint32_t s, const void* g) {
    asm volatile("cp.async.cg.shared.global [%0], [%1], 16;" :: "r"(s), "l"(g));
}
#define CP_COMMIT() asm volatile("cp.async.commit_group;" ::: "memory")
#define CP_WAIT(n)  asm volatile("cp.async.wait_group %0;" :: "n"(n) : "memory")

// ---------------------------------------------------------------------------
// presplit: fp32 -> (hi, lo) bf16
// ---------------------------------------------------------------------------
__global__ void presplit(const float* __restrict__ in, __nv_bfloat16* __restrict__ hi,
                         __nv_bfloat16* __restrict__ lo, int n4)
{
    int i = blockIdx.x * blockDim.x + threadIdx.x;
    const int stride = gridDim.x * blockDim.x;
    for (; i < n4; i += stride) {
        float4 v = ((const float4*)in)[i];
        uint32_t h0, l0, h1, l1;
        split2(v.x, v.y, h0, l0); split2(v.z, v.w, h1, l1);
        ((uint2*)hi)[i] = make_uint2(h0, h1);
        ((uint2*)lo)[i] = make_uint2(l0, l1);
    }
}

// ---------------------------------------------------------------------------
// Pre-split bf16 tensor-core GEMM: C[M,Ntot] = A * Bw^T + bias
// Operands already split hi/lo (bf16, K-major). BM=BN=128, BK=32,
// 256 threads (8 warps 4x2, warp tile 32x64), cp.async double buffer.
// ---------------------------------------------------------------------------
#define GST 40                         // smem row stride in bf16 (80 bytes)
#define GARR (128 * GST * 2)           // bytes per array  = 10240
#define GSTAGE (4 * GARR)              // bytes per stage  = 40960

template<bool SPLIT_OUT>
__global__ __launch_bounds__(256, 2)
void gemm_bf16ps(const __nv_bfloat16* __restrict__ Ahg, const __nv_bfloat16* __restrict__ Alg,
                 const __nv_bfloat16* __restrict__ Bhg, const __nv_bfloat16* __restrict__ Blg,
                 const float* __restrict__ bias,
                 float* __restrict__ Cf, __nv_bfloat16* __restrict__ Ch,
                 __nv_bfloat16* __restrict__ Cl, int Ntot, int K)
{
    extern __shared__ char dsm[];

    const int tid = threadIdx.x, lane = tid & 31, wid = tid >> 5;
    const int wm = wid & 3, wn = wid >> 2;
    const int row0 = blockIdx.y * 128, col0 = blockIdx.x * 128;

    float acc[2][8][4];
#pragma unroll
    for (int mt = 0; mt < 2; mt++)
#pragma unroll
        for (int nt = 0; nt < 8; nt++)
#pragma unroll
            for (int i = 0; i < 4; i++) acc[mt][nt][i] = 0.f;

    // prefetch one stage: A/B tiles 128 rows x 32 k (hi+lo), 16B chunks
    auto prefetch = [&](int it, int s) {
        char* base = dsm + s * GSTAGE;
#pragma unroll
        for (int i = 0; i < 2; i++) {
            const int c = tid + i * 256;          // 0..511
            const int r = c >> 2, sub = c & 3;
            const uint32_t so = r * 80 + sub * 16;
            const size_t ga = (size_t)(row0 + r) * K + it * 32 + sub * 8;
            const size_t gb = (size_t)(col0 + r) * K + it * 32 + sub * 8;
            cpa16(su32(base + so),            Ahg + ga);
            cpa16(su32(base + GARR + so),     Alg + ga);
            cpa16(su32(base + 2 * GARR + so), Bhg + gb);
            cpa16(su32(base + 3 * GARR + so), Blg + gb);
        }
    };

    const int nit = K / 32;
    prefetch(0, 0);
    CP_COMMIT();

    for (int it = 0; it < nit; it++) {
        const int s = it & 1;
        if (it + 1 < nit) prefetch(it + 1, s ^ 1);
        CP_COMMIT();
        CP_WAIT(1);
        __syncthreads();

        const __nv_bfloat16* sAh = (const __nv_bfloat16*)(dsm + s * GSTAGE);
        const __nv_bfloat16* sAl = (const __nv_bfloat16*)(dsm + s * GSTAGE + GARR);
        const __nv_bfloat16* sBh = (const __nv_bfloat16*)(dsm + s * GSTAGE + 2 * GARR);
        const __nv_bfloat16* sBl = (const __nv_bfloat16*)(dsm + s * GSTAGE + 3 * GARR);

#pragma unroll
        for (int kk = 0; kk < 32; kk += 16) {
            uint32_t ah[2][4], al[2][4];
            const int cl = kk + ((lane >> 4) << 3);
#pragma unroll
            for (int mt = 0; mt < 2; mt++) {
                const int rw = wm * 32 + mt * 16 + (lane & 15);
                ldsm4(ah[mt], su32(&sAh[rw * GST + cl]));
                ldsm4(al[mt], su32(&sAl[rw * GST + cl]));
            }
#pragma unroll
            for (int np = 0; np < 4; np++) {
                uint32_t bh[4], bl[4];
                const int rw = wn * 64 + np * 16 + (lane & 15);
                ldsm4(bh, su32(&sBh[rw * GST + cl]));
                ldsm4(bl, su32(&sBl[rw * GST + cl]));
#pragma unroll
                for (int mt = 0; mt < 2; mt++) {
#pragma unroll
                    for (int sub = 0; sub < 2; sub++) {
                        float* c = acc[mt][np * 2 + sub];
                        mma16816(c, ah[mt], bh[sub], bh[sub + 2]);
                        mma16816(c, ah[mt], bl[sub], bl[sub + 2]);
                        mma16816(c, al[mt], bh[sub], bh[sub + 2]);
                    }
                }
            }
        }
        __syncthreads();
    }

    // epilogue
    const int g = lane >> 2, tq = lane & 3;
#pragma unroll
    for (int mt = 0; mt < 2; mt++) {
        const int r = row0 + wm * 32 + mt * 16 + g;
#pragma unroll
        for (int nt = 0; nt < 8; nt++) {
            const int c = col0 + wn * 64 + nt * 8 + tq * 2;
            float2 bi = *(const float2*)(bias + c);
            const float f0 = acc[mt][nt][0] + bi.x, f1 = acc[mt][nt][1] + bi.y;
            const float f2 = acc[mt][nt][2] + bi.x, f3 = acc[mt][nt][3] + bi.y;
            if (SPLIT_OUT) {
                uint32_t hh, ll;
                split2(f0, f1, hh, ll);
                *(uint32_t*)&Ch[(size_t)r * Ntot + c] = hh;
                *(uint32_t*)&Cl[(size_t)r * Ntot + c] = ll;
                split2(f2, f3, hh, ll);
                *(uint32_t*)&Ch[(size_t)(r + 8) * Ntot + c] = hh;
                *(uint32_t*)&Cl[(size_t)(r + 8) * Ntot + c] = ll;
            } else {
                *(float2*)(Cf + (size_t)r * Ntot + c)       = make_float2(f0, f1);
                *(float2*)(Cf + (size_t)(r + 8) * Ntot + c) = make_float2(f2, f3);
            }
        }
    }
}

// ---------------------------------------------------------------------------
// Flash attention, pre-split bf16, cp.async pipelined.
// 256 threads (8 warps), 128 q-rows per block, one (b,h).
// K single-buffered, V double-buffered; next tile's K/V issued right after
// S-compute releases K; wait lands after PV (latency hidden).
// smem: Kh,Kl + Vh,Vl x2 stages, stride 72 elems (144B rows) = 108 KB.
// ---------------------------------------------------------------------------
#define AST 72
#define AARR (128 * AST * 2)   // 18432 bytes per array

__global__ __launch_bounds__(256)
void attn_bf16ps(const __nv_bfloat16* __restrict__ qkvh,
                 const __nv_bfloat16* __restrict__ qkvl,
                 __nv_bfloat16* __restrict__ attnh,
                 __nv_bfloat16* __restrict__ attnl)
{
    extern __shared__ char dsm[];
    __nv_bfloat16* Kh = (__nv_bfloat16*)dsm;
    __nv_bfloat16* Kl = (__nv_bfloat16*)(dsm + AARR);

    const int tid = threadIdx.x, lane = tid & 31, wid = tid >> 5;
    const int b = blockIdx.y >> 4, h = blockIdx.y & 15;
    const int q0 = blockIdx.x * 128;
    const float scale = 0.125f;

    const size_t hb = (size_t)b * T_ * QKV_COLS + h * DH_;
    const __nv_bfloat16* qbh = qkvh + hb;
    const __nv_bfloat16* qbl = qkvl + hb;
    const __nv_bfloat16* kbh = qbh + D_;
    const __nv_bfloat16* kbl = qbl + D_;
    const __nv_bfloat16* vbh = qbh + 2 * D_;
    const __nv_bfloat16* vbl = qbl + 2 * D_;

    auto loadK = [&](int kt) {
#pragma unroll
        for (int i = 0; i < 4; i++) {
            const int c = tid + i * 256;
            const int r = c >> 3, sub = c & 7;
            const uint32_t so = r * 144 + sub * 16;
            const size_t g = (size_t)(kt * 128 + r) * QKV_COLS + sub * 8;
            cpa16(su32(dsm + so),        kbh + g);
            cpa16(su32(dsm + AARR + so), kbl + g);
        }
    };
    auto loadV = [&](int kt, int s) {
        char* vb = dsm + 2 * AARR + s * 2 * AARR;
#pragma unroll
        for (int i = 0; i < 4; i++) {
            const int c = tid + i * 256;
            const int r = c >> 3, sub = c & 7;
            const uint32_t so = r * 144 + sub * 16;
            const size_t g = (size_t)(kt * 128 + r) * QKV_COLS + sub * 8;
            cpa16(su32(vb + so),        vbh + g);
            cpa16(su32(vb + AARR + so), vbl + g);
        }
    };

    // ---- stage Q into K buffers, pull fragments ----
#pragma unroll
    for (int i = 0; i < 4; i++) {
        const int c = tid + i * 256;
        const int r = c >> 3, sub = c & 7;
        const uint32_t so = r * 144 + sub * 16;
        const size_t g = (size_t)(q0 + r) * QKV_COLS + sub * 8;
        cpa16(su32(dsm + so),        qbh + g);
        cpa16(su32(dsm + AARR + so), qbl + g);
    }
    CP_COMMIT(); CP_WAIT(0); __syncthreads();

    uint32_t qh[4][4], ql[4][4];
#pragma unroll
    for (int kc = 0; kc < 4; kc++) {
        const int rw = wid * 16 + (lane & 15);
        const int cl = kc * 16 + ((lane >> 4) << 3);
        ldsm4(qh[kc], su32(&Kh[rw * AST + cl]));
        ldsm4(ql[kc], su32(&Kl[rw * AST + cl]));
    }
    __syncthreads();

    loadK(0); loadV(0, 0);
    CP_COMMIT(); CP_WAIT(0); __syncthreads();

    float oacc[8][4];
#pragma unroll
    for (int nt = 0; nt < 8; nt++)
#pragma unroll
        for (int i = 0; i < 4; i++) oacc[nt][i] = 0.f;
    float mr0 = -INFINITY, mr1 = -INFINITY, lr0 = 0.f, lr1 = 0.f;

    for (int kt = 0; kt < 16; kt++) {
        const int vs = kt & 1;

        // ---- S = Q K^T ----
        float sacc[16][4];
#pragma unroll
        for (int nt = 0; nt < 16; nt++)
#pragma unroll
            for (int i = 0; i < 4; i++) sacc[nt][i] = 0.f;

#pragma unroll
        for (int np = 0; np < 8; np++) {
#pragma unroll
            for (int kc = 0; kc < 4; kc++) {
                uint32_t bh[4], bl[4];
                const int rw = np * 16 + (lane & 15);
                const int cl = kc * 16 + ((lane >> 4) << 3);
                ldsm4(bh, su32(&Kh[rw * AST + cl]));
                ldsm4(bl, su32(&Kl[rw * AST + cl]));
                mma16816(sacc[np * 2],     qh[kc], bh[0], bh[2]);
                mma16816(sacc[np * 2],     qh[kc], bl[0], bl[2]);
                mma16816(sacc[np * 2],     ql[kc], bh[0], bh[2]);
                mma16816(sacc[np * 2 + 1], qh[kc], bh[1], bh[3]);
                mma16816(sacc[np * 2 + 1], qh[kc], bl[1], bl[3]);
                mma16816(sacc[np * 2 + 1], ql[kc], bh[1], bh[3]);
            }
        }
        __syncthreads();                  // all warps done reading K smem
        if (kt < 15) {                    // prefetch next tile (hidden by softmax+PV)
            loadK(kt + 1);
            loadV(kt + 1, vs ^ 1);
            CP_COMMIT();
        }

        // ---- online softmax ----
        float tm0 = -INFINITY, tm1 = -INFINITY;
#pragma unroll
        for (int nt = 0; nt < 16; nt++) {
            tm0 = fmaxf(tm0, fmaxf(sacc[nt][0], sacc[nt][1]));
            tm1 = fmaxf(tm1, fmaxf(sacc[nt][2], sacc[nt][3]));
        }
        tm0 = fmaxf(tm0, __shfl_xor_sync(0xffffffffu, tm0, 1));
        tm0 = fmaxf(tm0, __shfl_xor_sync(0xffffffffu, tm0, 2));
        tm1 = fmaxf(tm1, __shfl_xor_sync(0xffffffffu, tm1, 1));
        tm1 = fmaxf(tm1, __shfl_xor_sync(0xffffffffu, tm1, 2));

        const float nm0 = fmaxf(mr0, tm0 * scale);
        const float nm1 = fmaxf(mr1, tm1 * scale);
        const float al0 = __expf(mr0 - nm0);
        const float al1 = __expf(mr1 - nm1);
        mr0 = nm0; mr1 = nm1;
#pragma unroll
        for (int nt = 0; nt < 8; nt++) {
            oacc[nt][0] *= al0; oacc[nt][1] *= al0;
            oacc[nt][2] *= al1; oacc[nt][3] *= al1;
        }

        float rs0 = 0.f, rs1 = 0.f;
        uint32_t php[8][4], plp[8][4];
#pragma unroll
        for (int j = 0; j < 8; j++) {
            const float p00 = __expf(fmaf(sacc[2 * j][0],     scale, -nm0));
            const float p01 = __expf(fmaf(sacc[2 * j][1],     scale, -nm0));
            const float p10 = __expf(fmaf(sacc[2 * j][2],     scale, -nm1));
            const float p11 = __expf(fmaf(sacc[2 * j][3],     scale, -nm1));
            const float r00 = __expf(fmaf(sacc[2 * j + 1][0], scale, -nm0));
            const float r01 = __expf(fmaf(sacc[2 * j + 1][1], scale, -nm0));
            const float r10 = __expf(fmaf(sacc[2 * j + 1][2], scale, -nm1));
            const float r11 = __expf(fmaf(sacc[2 * j + 1][3], scale, -nm1));
            rs0 += (p00 + p01) + (r00 + r01);
            rs1 += (p10 + p11) + (r10 + r11);
            split2(p00, p01, php[j][0], plp[j][0]);
            split2(p10, p11, php[j][1], plp[j][1]);
            split2(r00, r01, php[j][2], plp[j][2]);
            split2(r10, r11, php[j][3], plp[j][3]);
        }
        rs0 += __shfl_xor_sync(0xffffffffu, rs0, 1);
        rs0 += __shfl_xor_sync(0xffffffffu, rs0, 2);
        rs1 += __shfl_xor_sync(0xffffffffu, rs1, 1);
        rs1 += __shfl_xor_sync(0xffffffffu, rs1, 2);
        lr0 = lr0 * al0 + rs0;
        lr1 = lr1 * al1 + rs1;

        // ---- O += P V ----
        const __nv_bfloat16* Vh = (const __nv_bfloat16*)(dsm + 2 * AARR + vs * 2 * AARR);
        const __nv_bfloat16* Vl = (const __nv_bfloat16*)(dsm + 3 * AARR + vs * 2 * AARR);
#pragma unroll
        for (int j = 0; j < 8; j++) {
#pragma unroll
            for (int dp = 0; dp < 4; dp++) {
                uint32_t vhf[4], vlf[4];
                const int rw = j * 16 + (lane & 7) + ((lane >> 3) & 1) * 8;
                const int cl = dp * 16 + ((lane >> 4) << 3);
                ldsm4t(vhf, su32(&Vh[rw * AST + cl]));
                ldsm4t(vlf, su32(&Vl[rw * AST + cl]));
                mma16816(oacc[dp * 2],     php[j], vhf[0], vhf[1]);
                mma16816(oacc[dp * 2],     php[j], vlf[0], vlf[1]);
                mma16816(oacc[dp * 2],     plp[j], vhf[0], vhf[1]);
                mma16816(oacc[dp * 2 + 1], php[j], vhf[2], vhf[3]);
                mma16816(oacc[dp * 2 + 1], php[j], vlf[2], vlf[3]);
                mma16816(oacc[dp * 2 + 1], plp[j], vhf[2], vhf[3]);
            }
        }

        if (kt < 15) { CP_WAIT(0); __syncthreads(); }
    }

    // ---- epilogue: normalize, split, store hi/lo ----
    const float inv0 = 1.f / lr0, inv1 = 1.f / lr1;
    const int g = lane >> 2, tq = lane & 3;
    const size_t r0o = (size_t)(b * T_ + q0 + wid * 16 + g);
#pragma unroll
    for (int nt = 0; nt < 8; nt++) {
        const int col = h * DH_ + nt * 8 + tq * 2;
        uint32_t hh, ll;
        split2(oacc[nt][0] * inv0, oacc[nt][1] * inv0, hh, ll);
        *(uint32_t*)&attnh[r0o * D_ + col] = hh;
        *(uint32_t*)&attnl[r0o * D_ + col] = ll;
        split2(oacc[nt][2] * inv1, oacc[nt][3] * inv1, hh, ll);
        *(uint32_t*)&attnh[(r0o + 8) * D_ + col] = hh;
        *(uint32_t*)&attnl[(r0o + 8) * D_ + col] = ll;
    }
}

// ---------------------------------------------------------------------------
// kernel_launch
// ---------------------------------------------------------------------------
extern "C" void kernel_launch(void* const* d_in, const int* in_sizes, int n_in,
                              void* d_out, int out_size)
{
    const float* x     = (const float*)d_in[0];
    const float* w_qkv = (const float*)d_in[1];
    const float* b_qkv = (const float*)d_in[2];
    const float* w_out = (const float*)d_in[3];
    const float* b_out = (const float*)d_in[4];
    float* out = (float*)d_out;

    __nv_bfloat16 *xh, *xl, *wqh, *wql, *woh, *wol, *qh, *ql, *ah, *al;
    cudaGetSymbolAddress((void**)&xh,  g_x_h);    cudaGetSymbolAddress((void**)&xl,  g_x_l);
    cudaGetSymbolAddress((void**)&wqh, g_wqkv_h); cudaGetSymbolAddress((void**)&wql, g_wqkv_l);
    cudaGetSymbolAddress((void**)&woh, g_wout_h); cudaGetSymbolAddress((void**)&wol, g_wout_l);
    cudaGetSymbolAddress((void**)&qh,  g_qkv_h);  cudaGetSymbolAddress((void**)&ql,  g_qkv_l);
    cudaGetSymbolAddress((void**)&ah,  g_attn_h); cudaGetSymbolAddress((void**)&al,  g_attn_l);

    // 0) pre-split inputs
    presplit<<<2048, 256>>>(x,     xh,  xl,  NTOK * D_ / 4);
    presplit<<<1024, 256>>>(w_qkv, wqh, wql, QKV_COLS * D_ / 4);
    presplit<<<512,  256>>>(w_out, woh, wol, D_ * D_ / 4);

    const int gsmem = 2 * GSTAGE;  // 81920
    cudaFuncSetAttribute(gemm_bf16ps<true>,
                         cudaFuncAttributeMaxDynamicSharedMemorySize, gsmem);
    cudaFuncSetAttribute(gemm_bf16ps<false>,
                         cudaFuncAttributeMaxDynamicSharedMemorySize, gsmem);

    // 1) QKV projection, split output
    {
        dim3 grid(QKV_COLS / 128, NTOK / 128);
        gemm_bf16ps<true><<<grid, 256, gsmem>>>(xh, xl, wqh, wql, b_qkv,
                                                nullptr, qh, ql, QKV_COLS, D_);
    }

    // 2) Flash attention, split output
    {
        const int asmem = 6 * AARR;  // 110592
        cudaFuncSetAttribute(attn_bf16ps,
                             cudaFuncAttributeMaxDynamicSharedMemorySize, asmem);
        dim3 grid(T_ / 128, B_ * H_);
        attn_bf16ps<<<grid, 256, asmem>>>(qh, ql, ah, al);
    }

    // 3) Output projection, fp32 output
    {
        dim3 grid(D_ / 128, NTOK / 128);
        gemm_bf16ps<false><<<grid, 256, gsmem>>>(ah, al, woh, wol, b_out,
                                                 out, nullptr, nullptr, D_, D_);
    }
}

// round 5
// speedup vs baseline: 4.0952x; 1.3334x over previous
#include <cuda_runtime.h>
#include <cuda_fp16.h>
#include <math.h>
#include <stdint.h>

#define B_   4
#define T_   2048
#define D_   1024
#define H_   16
#define DH_  64
#define NTOK (B_ * T_)          // 8192
#define QKV_COLS (3 * D_)       // 3072

// ---------------------------------------------------------------------------
// fp16 global scratch (allocation-free rule: __device__ globals)
// ---------------------------------------------------------------------------
__device__ __half g_x_h[(size_t)NTOK * D_],  g_x_l[(size_t)NTOK * D_];
__device__ __half g_wqkv_h[(size_t)QKV_COLS * D_];
__device__ __half g_wout_h[(size_t)D_ * D_];
__device__ __half g_qkv_h[(size_t)NTOK * QKV_COLS];
__device__ __half g_qkv_l[(size_t)NTOK * QKV_COLS];   // only Q third used
__device__ __half g_attn_h[(size_t)NTOK * D_], g_attn_l[(size_t)NTOK * D_];

// ---------------------------------------------------------------------------
// helpers
// ---------------------------------------------------------------------------
__device__ __forceinline__ uint32_t su32(const void* p) {
    return (uint32_t)__cvta_generic_to_shared(p);
}
__device__ __forceinline__ void ldsm4(uint32_t* r, uint32_t a) {
    asm volatile("ldmatrix.sync.aligned.m8n8.x4.shared.b16 {%0,%1,%2,%3}, [%4];"
        : "=r"(r[0]), "=r"(r[1]), "=r"(r[2]), "=r"(r[3]) : "r"(a));
}
__device__ __forceinline__ void ldsm4t(uint32_t* r, uint32_t a) {
    asm volatile("ldmatrix.sync.aligned.m8n8.x4.trans.shared.b16 {%0,%1,%2,%3}, [%4];"
        : "=r"(r[0]), "=r"(r[1]), "=r"(r[2]), "=r"(r[3]) : "r"(a));
}
__device__ __forceinline__ void mmaf16(float* c, const uint32_t* a,
                                       uint32_t b0, uint32_t b1) {
    asm volatile(
        "mma.sync.aligned.m16n8k16.row.col.f32.f16.f16.f32 "
        "{%0,%1,%2,%3},{%4,%5,%6,%7},{%8,%9},{%0,%1,%2,%3};"
        : "+f"(c[0]), "+f"(c[1]), "+f"(c[2]), "+f"(c[3])
        : "r"(a[0]), "r"(a[1]), "r"(a[2]), "r"(a[3]), "r"(b0), "r"(b1));
}
__device__ __forceinline__ uint32_t pkh(float x, float y) {
    __half2 t = __floats2half2_rn(x, y);
    return *reinterpret_cast<uint32_t*>(&t);
}
// split pair of floats into (hi, lo) packed fp16x2
__device__ __forceinline__ void split2h(float x, float y, uint32_t& hi, uint32_t& lo) {
    const float hx = __half2float(__float2half_rn(x));
    const float hy = __half2float(__float2half_rn(y));
    hi = pkh(hx, hy);
    lo = pkh(x - hx, y - hy);
}
__device__ __forceinline__ void cpa16(uint32_t s, const void* g) {
    asm volatile("cp.async.cg.shared.global [%0], [%1], 16;" :: "r"(s), "l"(g));
}
#define CP_COMMIT() asm volatile("cp.async.commit_group;" ::: "memory")
#define CP_WAIT(n)  asm volatile("cp.async.wait_group %0;" :: "n"(n) : "memory")

// ---------------------------------------------------------------------------
// presplit: fp32 -> (hi, lo) fp16 ; presingle: fp32 -> fp16
// ---------------------------------------------------------------------------
__global__ void presplit(const float* __restrict__ in, __half* __restrict__ hi,
                         __half* __restrict__ lo, int n4)
{
    int i = blockIdx.x * blockDim.x + threadIdx.x;
    const int stride = gridDim.x * blockDim.x;
    for (; i < n4; i += stride) {
        float4 v = ((const float4*)in)[i];
        uint32_t h0, l0, h1, l1;
        split2h(v.x, v.y, h0, l0); split2h(v.z, v.w, h1, l1);
        ((uint2*)hi)[i] = make_uint2(h0, h1);
        ((uint2*)lo)[i] = make_uint2(l0, l1);
    }
}
__global__ void presingle(const float* __restrict__ in, __half* __restrict__ hi, int n4)
{
    int i = blockIdx.x * blockDim.x + threadIdx.x;
    const int stride = gridDim.x * blockDim.x;
    for (; i < n4; i += stride) {
        float4 v = ((const float4*)in)[i];
        ((uint2*)hi)[i] = make_uint2(pkh(v.x, v.y), pkh(v.z, v.w));
    }
}

// ---------------------------------------------------------------------------
// fp16 2-term GEMM: C[M,Ntot] = (Ah+Al) * Bh^T + bias
// BM=BN=128, BK=32, 256 threads (8 warps 4x2, warp tile 32x64),
// cp.async double buffer. 2 MMAs per logical k16 tile.
// SPLITQ: write fp16 hi everywhere + fp16 lo for cols < D_ (Q third);
// else fp32 out.
// ---------------------------------------------------------------------------
#define GST 40                       // smem row stride in fp16 (80 bytes)
#define GARR (128 * GST * 2)         // 10240 bytes per array
#define GSTAGE (3 * GARR)            // 30720 bytes per stage

template<bool SPLITQ>
__global__ __launch_bounds__(256, 2)
void gemm_f16s(const __half* __restrict__ Ahg, const __half* __restrict__ Alg,
               const __half* __restrict__ Bhg, const float* __restrict__ bias,
               float* __restrict__ Cf, __half* __restrict__ Ch,
               __half* __restrict__ Cl, int Ntot, int K)
{
    extern __shared__ char dsm[];

    const int tid = threadIdx.x, lane = tid & 31, wid = tid >> 5;
    const int wm = wid & 3, wn = wid >> 2;
    const int row0 = blockIdx.y * 128, col0 = blockIdx.x * 128;

    float acc[2][8][4];
#pragma unroll
    for (int mt = 0; mt < 2; mt++)
#pragma unroll
        for (int nt = 0; nt < 8; nt++)
#pragma unroll
            for (int i = 0; i < 4; i++) acc[mt][nt][i] = 0.f;

    auto prefetch = [&](int it, int s) {
        char* base = dsm + s * GSTAGE;
#pragma unroll
        for (int i = 0; i < 2; i++) {
            const int id = tid + i * 256;        // 0..511
            const int r = id >> 2, c = id & 3;
            const uint32_t so = r * 80 + c * 16;
            const size_t ga = (size_t)(row0 + r) * K + it * 32 + c * 8;
            const size_t gb = (size_t)(col0 + r) * K + it * 32 + c * 8;
            cpa16(su32(base + so),            Ahg + ga);
            cpa16(su32(base + GARR + so),     Alg + ga);
            cpa16(su32(base + 2 * GARR + so), Bhg + gb);
        }
    };

    const int nit = K / 32;
    prefetch(0, 0);
    CP_COMMIT();

    for (int it = 0; it < nit; it++) {
        const int s = it & 1;
        if (it + 1 < nit) prefetch(it + 1, s ^ 1);
        CP_COMMIT();
        CP_WAIT(1);
        __syncthreads();

        const __half* sAh = (const __half*)(dsm + s * GSTAGE);
        const __half* sAl = (const __half*)(dsm + s * GSTAGE + GARR);
        const __half* sBh = (const __half*)(dsm + s * GSTAGE + 2 * GARR);

#pragma unroll
        for (int kk = 0; kk < 32; kk += 16) {
            uint32_t ah[2][4], al[2][4];
            const int cl = kk + ((lane >> 4) << 3);
#pragma unroll
            for (int mt = 0; mt < 2; mt++) {
                const int rw = wm * 32 + mt * 16 + (lane & 15);
                ldsm4(ah[mt], su32(&sAh[rw * GST + cl]));
                ldsm4(al[mt], su32(&sAl[rw * GST + cl]));
            }
#pragma unroll
            for (int np = 0; np < 4; np++) {
                uint32_t bh[4];
                const int rw = wn * 64 + np * 16 + (lane & 15);
                ldsm4(bh, su32(&sBh[rw * GST + cl]));
#pragma unroll
                for (int mt = 0; mt < 2; mt++) {
#pragma unroll
                    for (int sub = 0; sub < 2; sub++) {
                        float* c = acc[mt][np * 2 + sub];
                        mmaf16(c, ah[mt], bh[sub], bh[sub + 2]);
                        mmaf16(c, al[mt], bh[sub], bh[sub + 2]);
                    }
                }
            }
        }
        __syncthreads();
    }

    // epilogue
    const int g = lane >> 2, tq = lane & 3;
#pragma unroll
    for (int mt = 0; mt < 2; mt++) {
        const int r = row0 + wm * 32 + mt * 16 + g;
#pragma unroll
        for (int nt = 0; nt < 8; nt++) {
            const int c = col0 + wn * 64 + nt * 8 + tq * 2;
            float2 bi = *(const float2*)(bias + c);
            const float f0 = acc[mt][nt][0] + bi.x, f1 = acc[mt][nt][1] + bi.y;
            const float f2 = acc[mt][nt][2] + bi.x, f3 = acc[mt][nt][3] + bi.y;
            if (SPLITQ) {
                uint32_t hh, ll;
                split2h(f0, f1, hh, ll);
                *(uint32_t*)&Ch[(size_t)r * Ntot + c] = hh;
                if (c < D_) *(uint32_t*)&Cl[(size_t)r * Ntot + c] = ll;
                split2h(f2, f3, hh, ll);
                *(uint32_t*)&Ch[(size_t)(r + 8) * Ntot + c] = hh;
                if (c < D_) *(uint32_t*)&Cl[(size_t)(r + 8) * Ntot + c] = ll;
            } else {
                *(float2*)(Cf + (size_t)r * Ntot + c)       = make_float2(f0, f1);
                *(float2*)(Cf + (size_t)(r + 8) * Ntot + c) = make_float2(f2, f3);
            }
        }
    }
}

// ---------------------------------------------------------------------------
// Flash attention, fp16 2-term (Q split / K single, P split / V single).
// 256 threads (8 warps), 128 q-rows per block, one (b,h).
// smem: Kh [128][72] + Vh x2 stages = 54 KB -> 2 CTAs/SM.
// ---------------------------------------------------------------------------
#define AST 72
#define AARR (128 * AST * 2)   // 18432 bytes per array

__global__ __launch_bounds__(256, 2)
void attn_f16s(const __half* __restrict__ qkvh, const __half* __restrict__ qkvl,
               __half* __restrict__ attnh, __half* __restrict__ attnl)
{
    extern __shared__ char dsm[];
    __half* Kh = (__half*)dsm;

    const int tid = threadIdx.x, lane = tid & 31, wid = tid >> 5;
    const int b = blockIdx.y >> 4, h = blockIdx.y & 15;
    const int q0 = blockIdx.x * 128;
    const float scale = 0.125f;   // 1/sqrt(64)

    const size_t hb = (size_t)b * T_ * QKV_COLS + h * DH_;
    const __half* qbh = qkvh + hb;
    const __half* qbl = qkvl + hb;
    const __half* kbh = qbh + D_;
    const __half* vbh = qbh + 2 * D_;

    // 4 chunks per thread: 128 rows x 8 chunks of 16B (row stride 144B)
    auto loadTile = [&](const __half* src, char* dstbase, int row_off) {
#pragma unroll
        for (int i = 0; i < 4; i++) {
            const int id = tid + i * 256;
            const int r = id >> 3, c = id & 7;
            const uint32_t so = r * 144 + c * 16;
            const size_t g = (size_t)(row_off + r) * QKV_COLS + c * 8;
            cpa16(su32(dstbase + so), src + g);
        }
    };

    // ---- stage Qh into Kh buf, Ql into V0 buf; pull fragments ----
    loadTile(qbh, dsm, q0);
    loadTile(qbl, dsm + AARR, q0);
    CP_COMMIT(); CP_WAIT(0); __syncthreads();

    uint32_t qh[4][4], ql[4][4];
    {
        const __half* Ql = (const __half*)(dsm + AARR);
#pragma unroll
        for (int kc = 0; kc < 4; kc++) {
            const int rw = wid * 16 + (lane & 15);
            const int cl = kc * 16 + ((lane >> 4) << 3);
            ldsm4(qh[kc], su32(&Kh[rw * AST + cl]));
            ldsm4(ql[kc], su32(&Ql[rw * AST + cl]));
        }
    }
    __syncthreads();

    loadTile(kbh, dsm, 0);
    loadTile(vbh, dsm + AARR, 0);
    CP_COMMIT(); CP_WAIT(0); __syncthreads();

    float oacc[8][4];
#pragma unroll
    for (int nt = 0; nt < 8; nt++)
#pragma unroll
        for (int i = 0; i < 4; i++) oacc[nt][i] = 0.f;
    float mr0 = -INFINITY, mr1 = -INFINITY, lr0 = 0.f, lr1 = 0.f;

    for (int kt = 0; kt < 16; kt++) {
        const int vs = kt & 1;

        // ---- S = Q K^T ----
        float sacc[16][4];
#pragma unroll
        for (int nt = 0; nt < 16; nt++)
#pragma unroll
            for (int i = 0; i < 4; i++) sacc[nt][i] = 0.f;

#pragma unroll
        for (int np = 0; np < 8; np++) {
#pragma unroll
            for (int kc = 0; kc < 4; kc++) {
                uint32_t bh[4];
                const int rw = np * 16 + (lane & 15);
                const int cl = kc * 16 + ((lane >> 4) << 3);
                ldsm4(bh, su32(&Kh[rw * AST + cl]));
                mmaf16(sacc[np * 2],     qh[kc], bh[0], bh[2]);
                mmaf16(sacc[np * 2],     ql[kc], bh[0], bh[2]);
                mmaf16(sacc[np * 2 + 1], qh[kc], bh[1], bh[3]);
                mmaf16(sacc[np * 2 + 1], ql[kc], bh[1], bh[3]);
            }
        }
        __syncthreads();                  // all warps done reading Kh
        if (kt < 15) {                    // prefetch next K and V
            loadTile(kbh, dsm, (kt + 1) * 128);
            loadTile(vbh, dsm + AARR + (vs ^ 1) * AARR, (kt + 1) * 128);
            CP_COMMIT();
        }

        // ---- online softmax ----
        float tm0 = -INFINITY, tm1 = -INFINITY;
#pragma unroll
        for (int nt = 0; nt < 16; nt++) {
            tm0 = fmaxf(tm0, fmaxf(sacc[nt][0], sacc[nt][1]));
            tm1 = fmaxf(tm1, fmaxf(sacc[nt][2], sacc[nt][3]));
        }
        tm0 = fmaxf(tm0, __shfl_xor_sync(0xffffffffu, tm0, 1));
        tm0 = fmaxf(tm0, __shfl_xor_sync(0xffffffffu, tm0, 2));
        tm1 = fmaxf(tm1, __shfl_xor_sync(0xffffffffu, tm1, 1));
        tm1 = fmaxf(tm1, __shfl_xor_sync(0xffffffffu, tm1, 2));

        const float nm0 = fmaxf(mr0, tm0 * scale);
        const float nm1 = fmaxf(mr1, tm1 * scale);
        const float al0 = __expf(mr0 - nm0);
        const float al1 = __expf(mr1 - nm1);
        mr0 = nm0; mr1 = nm1;
#pragma unroll
        for (int nt = 0; nt < 8; nt++) {
            oacc[nt][0] *= al0; oacc[nt][1] *= al0;
            oacc[nt][2] *= al1; oacc[nt][3] *= al1;
        }

        float rs0 = 0.f, rs1 = 0.f;
        uint32_t php[8][4], plp[8][4];
#pragma unroll
        for (int j = 0; j < 8; j++) {
            const float p00 = __expf(fmaf(sacc[2 * j][0],     scale, -nm0));
            const float p01 = __expf(fmaf(sacc[2 * j][1],     scale, -nm0));
            const float p10 = __expf(fmaf(sacc[2 * j][2],     scale, -nm1));
            const float p11 = __expf(fmaf(sacc[2 * j][3],     scale, -nm1));
            const float r00 = __expf(fmaf(sacc[2 * j + 1][0], scale, -nm0));
            const float r01 = __expf(fmaf(sacc[2 * j + 1][1], scale, -nm0));
            const float r10 = __expf(fmaf(sacc[2 * j + 1][2], scale, -nm1));
            const float r11 = __expf(fmaf(sacc[2 * j + 1][3], scale, -nm1));
            rs0 += (p00 + p01) + (r00 + r01);
            rs1 += (p10 + p11) + (r10 + r11);
            split2h(p00, p01, php[j][0], plp[j][0]);
            split2h(p10, p11, php[j][1], plp[j][1]);
            split2h(r00, r01, php[j][2], plp[j][2]);
            split2h(r10, r11, php[j][3], plp[j][3]);
        }
        rs0 += __shfl_xor_sync(0xffffffffu, rs0, 1);
        rs0 += __shfl_xor_sync(0xffffffffu, rs0, 2);
        rs1 += __shfl_xor_sync(0xffffffffu, rs1, 1);
        rs1 += __shfl_xor_sync(0xffffffffu, rs1, 2);
        lr0 = lr0 * al0 + rs0;
        lr1 = lr1 * al1 + rs1;

        // ---- O += P V ----
        const __half* Vh = (const __half*)(dsm + AARR + vs * AARR);
#pragma unroll
        for (int j = 0; j < 8; j++) {
#pragma unroll
            for (int dp = 0; dp < 4; dp++) {
                uint32_t vhf[4];
                const int rw = j * 16 + (lane & 7) + ((lane >> 3) & 1) * 8;
                const int cl = dp * 16 + ((lane >> 4) << 3);
                ldsm4t(vhf, su32(&Vh[rw * AST + cl]));
                mmaf16(oacc[dp * 2],     php[j], vhf[0], vhf[1]);
                mmaf16(oacc[dp * 2],     plp[j], vhf[0], vhf[1]);
                mmaf16(oacc[dp * 2 + 1], php[j], vhf[2], vhf[3]);
                mmaf16(oacc[dp * 2 + 1], plp[j], vhf[2], vhf[3]);
            }
        }

        if (kt < 15) { CP_WAIT(0); __syncthreads(); }
    }

    // ---- epilogue: normalize, split, store hi/lo fp16 ----
    const float inv0 = 1.f / lr0, inv1 = 1.f / lr1;
    const int g = lane >> 2, tq = lane & 3;
    const size_t r0o = (size_t)(b * T_ + q0 + wid * 16 + g);
#pragma unroll
    for (int nt = 0; nt < 8; nt++) {
        const int col = h * DH_ + nt * 8 + tq * 2;
        uint32_t hh, ll;
        split2h(oacc[nt][0] * inv0, oacc[nt][1] * inv0, hh, ll);
        *(uint32_t*)&attnh[r0o * D_ + col] = hh;
        *(uint32_t*)&attnl[r0o * D_ + col] = ll;
        split2h(oacc[nt][2] * inv1, oacc[nt][3] * inv1, hh, ll);
        *(uint32_t*)&attnh[(r0o + 8) * D_ + col] = hh;
        *(uint32_t*)&attnl[(r0o + 8) * D_ + col] = ll;
    }
}

// ---------------------------------------------------------------------------
// kernel_launch
// ---------------------------------------------------------------------------
extern "C" void kernel_launch(void* const* d_in, const int* in_sizes, int n_in,
                              void* d_out, int out_size)
{
    const float* x     = (const float*)d_in[0];
    const float* w_qkv = (const float*)d_in[1];
    const float* b_qkv = (const float*)d_in[2];
    const float* w_out = (const float*)d_in[3];
    const float* b_out = (const float*)d_in[4];
    float* out = (float*)d_out;

    __half *xh, *xl, *wqh, *woh, *qh, *ql, *ah, *al;
    cudaGetSymbolAddress((void**)&xh,  g_x_h);    cudaGetSymbolAddress((void**)&xl,  g_x_l);
    cudaGetSymbolAddress((void**)&wqh, g_wqkv_h);
    cudaGetSymbolAddress((void**)&woh, g_wout_h);
    cudaGetSymbolAddress((void**)&qh,  g_qkv_h);  cudaGetSymbolAddress((void**)&ql,  g_qkv_l);
    cudaGetSymbolAddress((void**)&ah,  g_attn_h); cudaGetSymbolAddress((void**)&al,  g_attn_l);

    // 0) pre-split / pre-round inputs
    presplit <<<2048, 256>>>(x,     xh,  xl, NTOK * D_ / 4);
    presingle<<<1024, 256>>>(w_qkv, wqh,     QKV_COLS * D_ / 4);
    presingle<<<512,  256>>>(w_out, woh,     D_ * D_ / 4);

    const int gsmem = 2 * GSTAGE;  // 61440
    cudaFuncSetAttribute(gemm_f16s<true>,
                         cudaFuncAttributeMaxDynamicSharedMemorySize, gsmem);
    cudaFuncSetAttribute(gemm_f16s<false>,
                         cudaFuncAttributeMaxDynamicSharedMemorySize, gsmem);

    // 1) QKV projection: hi fp16 everywhere, lo fp16 for Q columns
    {
        dim3 grid(QKV_COLS / 128, NTOK / 128);
        gemm_f16s<true><<<grid, 256, gsmem>>>(xh, xl, wqh, b_qkv,
                                              nullptr, qh, ql, QKV_COLS, D_);
    }

    // 2) Flash attention, split fp16 output
    {
        const int asmem = 3 * AARR;  // 55296
        cudaFuncSetAttribute(attn_f16s,
                             cudaFuncAttributeMaxDynamicSharedMemorySize, asmem);
        dim3 grid(T_ / 128, B_ * H_);
        attn_f16s<<<grid, 256, asmem>>>(qh, ql, ah, al);
    }

    // 3) Output projection, fp32 output
    {
        dim3 grid(D_ / 128, NTOK / 128);
        gemm_f16s<false><<<grid, 256, gsmem>>>(ah, al, woh, b_out,
                                               out, nullptr, nullptr, D_, D_);
    }
}

// round 6
// speedup vs baseline: 7.4844x; 1.8276x over previous
#include <cuda_runtime.h>
#include <cuda_fp16.h>
#include <math.h>
#include <stdint.h>

#define B_   4
#define T_   2048
#define D_   1024
#define H_   16
#define DH_  64
#define NTOK (B_ * T_)          // 8192
#define QKV_COLS (3 * D_)       // 3072

// ---------------------------------------------------------------------------
// fp16 global scratch (allocation-free rule: __device__ globals)
// ---------------------------------------------------------------------------
__device__ __half g_x_h[(size_t)NTOK * D_];
__device__ __half g_wqkv_h[(size_t)QKV_COLS * D_];
__device__ __half g_wout_h[(size_t)D_ * D_];
__device__ __half g_qkv_h[(size_t)NTOK * QKV_COLS];
__device__ __half g_attn_h[(size_t)NTOK * D_];

// ---------------------------------------------------------------------------
// helpers
// ---------------------------------------------------------------------------
__device__ __forceinline__ uint32_t su32(const void* p) {
    return (uint32_t)__cvta_generic_to_shared(p);
}
__device__ __forceinline__ void ldsm4(uint32_t* r, uint32_t a) {
    asm volatile("ldmatrix.sync.aligned.m8n8.x4.shared.b16 {%0,%1,%2,%3}, [%4];"
        : "=r"(r[0]), "=r"(r[1]), "=r"(r[2]), "=r"(r[3]) : "r"(a));
}
__device__ __forceinline__ void ldsm4t(uint32_t* r, uint32_t a) {
    asm volatile("ldmatrix.sync.aligned.m8n8.x4.trans.shared.b16 {%0,%1,%2,%3}, [%4];"
        : "=r"(r[0]), "=r"(r[1]), "=r"(r[2]), "=r"(r[3]) : "r"(a));
}
__device__ __forceinline__ void mmaf16(float* c, const uint32_t* a,
                                       uint32_t b0, uint32_t b1) {
    asm volatile(
        "mma.sync.aligned.m16n8k16.row.col.f32.f16.f16.f32 "
        "{%0,%1,%2,%3},{%4,%5,%6,%7},{%8,%9},{%0,%1,%2,%3};"
        : "+f"(c[0]), "+f"(c[1]), "+f"(c[2]), "+f"(c[3])
        : "r"(a[0]), "r"(a[1]), "r"(a[2]), "r"(a[3]), "r"(b0), "r"(b1));
}
__device__ __forceinline__ uint32_t pkh(float x, float y) {
    __half2 t = __floats2half2_rn(x, y);
    return *reinterpret_cast<uint32_t*>(&t);
}
__device__ __forceinline__ float ex2(float x) {
    float r;
    asm("ex2.approx.f32 %0, %1;" : "=f"(r) : "f"(x));
    return r;
}
__device__ __forceinline__ void cpa16(uint32_t s, const void* g) {
    asm volatile("cp.async.cg.shared.global [%0], [%1], 16;" :: "r"(s), "l"(g));
}
#define CP_COMMIT() asm volatile("cp.async.commit_group;" ::: "memory")
#define CP_WAIT(n)  asm volatile("cp.async.wait_group %0;" :: "n"(n) : "memory")

// ---------------------------------------------------------------------------
// presingle: fp32 -> fp16 (round-to-nearest)
// ---------------------------------------------------------------------------
__global__ void presingle(const float* __restrict__ in, __half* __restrict__ hi, int n4)
{
    int i = blockIdx.x * blockDim.x + threadIdx.x;
    const int stride = gridDim.x * blockDim.x;
    for (; i < n4; i += stride) {
        float4 v = ((const float4*)in)[i];
        ((uint2*)hi)[i] = make_uint2(pkh(v.x, v.y), pkh(v.z, v.w));
    }
}

// ---------------------------------------------------------------------------
// fp16 GEMM: C[M,Ntot] = A * Bw^T + bias  (single term)
// BM=BN=128, BK=32, 256 threads (8 warps 4x2, warp tile 32x64),
// cp.async double buffer. 1 MMA per logical k16 tile.
// ---------------------------------------------------------------------------
#define GST 40                       // smem row stride in fp16 (80 bytes)
#define GARR (128 * GST * 2)         // 10240 bytes per array
#define GSTAGE (2 * GARR)            // 20480 bytes per stage

template<bool WRITE_HALF>
__global__ __launch_bounds__(256, 2)
void gemm_f16(const __half* __restrict__ Ahg, const __half* __restrict__ Bhg,
              const float* __restrict__ bias,
              float* __restrict__ Cf, __half* __restrict__ Ch, int Ntot, int K)
{
    extern __shared__ char dsm[];

    const int tid = threadIdx.x, lane = tid & 31, wid = tid >> 5;
    const int wm = wid & 3, wn = wid >> 2;
    const int row0 = blockIdx.y * 128, col0 = blockIdx.x * 128;

    float acc[2][8][4];
#pragma unroll
    for (int mt = 0; mt < 2; mt++)
#pragma unroll
        for (int nt = 0; nt < 8; nt++)
#pragma unroll
            for (int i = 0; i < 4; i++) acc[mt][nt][i] = 0.f;

    auto prefetch = [&](int it, int s) {
        char* base = dsm + s * GSTAGE;
#pragma unroll
        for (int i = 0; i < 2; i++) {
            const int id = tid + i * 256;        // 0..511
            const int r = id >> 2, c = id & 3;
            const uint32_t so = r * 80 + c * 16;
            const size_t ga = (size_t)(row0 + r) * K + it * 32 + c * 8;
            const size_t gb = (size_t)(col0 + r) * K + it * 32 + c * 8;
            cpa16(su32(base + so),        Ahg + ga);
            cpa16(su32(base + GARR + so), Bhg + gb);
        }
    };

    const int nit = K / 32;
    prefetch(0, 0);
    CP_COMMIT();

    for (int it = 0; it < nit; it++) {
        const int s = it & 1;
        if (it + 1 < nit) prefetch(it + 1, s ^ 1);
        CP_COMMIT();
        CP_WAIT(1);
        __syncthreads();

        const __half* sAh = (const __half*)(dsm + s * GSTAGE);
        const __half* sBh = (const __half*)(dsm + s * GSTAGE + GARR);

#pragma unroll
        for (int kk = 0; kk < 32; kk += 16) {
            uint32_t ah[2][4];
            const int cl = kk + ((lane >> 4) << 3);
#pragma unroll
            for (int mt = 0; mt < 2; mt++) {
                const int rw = wm * 32 + mt * 16 + (lane & 15);
                ldsm4(ah[mt], su32(&sAh[rw * GST + cl]));
            }
#pragma unroll
            for (int np = 0; np < 4; np++) {
                uint32_t bh[4];
                const int rw = wn * 64 + np * 16 + (lane & 15);
                ldsm4(bh, su32(&sBh[rw * GST + cl]));
#pragma unroll
                for (int mt = 0; mt < 2; mt++) {
                    mmaf16(acc[mt][np * 2],     ah[mt], bh[0], bh[2]);
                    mmaf16(acc[mt][np * 2 + 1], ah[mt], bh[1], bh[3]);
                }
            }
        }
        __syncthreads();
    }

    // epilogue
    const int g = lane >> 2, tq = lane & 3;
#pragma unroll
    for (int mt = 0; mt < 2; mt++) {
        const int r = row0 + wm * 32 + mt * 16 + g;
#pragma unroll
        for (int nt = 0; nt < 8; nt++) {
            const int c = col0 + wn * 64 + nt * 8 + tq * 2;
            float2 bi = *(const float2*)(bias + c);
            const float f0 = acc[mt][nt][0] + bi.x, f1 = acc[mt][nt][1] + bi.y;
            const float f2 = acc[mt][nt][2] + bi.x, f3 = acc[mt][nt][3] + bi.y;
            if (WRITE_HALF) {
                *(uint32_t*)&Ch[(size_t)r * Ntot + c]       = pkh(f0, f1);
                *(uint32_t*)&Ch[(size_t)(r + 8) * Ntot + c] = pkh(f2, f3);
            } else {
                *(float2*)(Cf + (size_t)r * Ntot + c)       = make_float2(f0, f1);
                *(float2*)(Cf + (size_t)(r + 8) * Ntot + c) = make_float2(f2, f3);
            }
        }
    }
}

// ---------------------------------------------------------------------------
// Flash attention, fp16 single term, base-2 softmax.
// 256 threads (8 warps), 128 q-rows per block, one (b,h).
// smem: Kh [128][72] + Vh x2 stages = 54 KB -> 2 CTAs/SM.
// ---------------------------------------------------------------------------
#define AST 72
#define AARR (128 * AST * 2)   // 18432 bytes per array
#define C2   0.1803368801f     // (1/sqrt(64)) * log2(e)

__global__ __launch_bounds__(256, 2)
void attn_f16(const __half* __restrict__ qkvh, __half* __restrict__ attnh)
{
    extern __shared__ char dsm[];
    __half* Kh = (__half*)dsm;

    const int tid = threadIdx.x, lane = tid & 31, wid = tid >> 5;
    const int b = blockIdx.y >> 4, h = blockIdx.y & 15;
    const int q0 = blockIdx.x * 128;

    const size_t hb = (size_t)b * T_ * QKV_COLS + h * DH_;
    const __half* qbh = qkvh + hb;
    const __half* kbh = qbh + D_;
    const __half* vbh = qbh + 2 * D_;

    auto loadTile = [&](const __half* src, char* dstbase, int row_off) {
#pragma unroll
        for (int i = 0; i < 4; i++) {
            const int id = tid + i * 256;
            const int r = id >> 3, c = id & 7;
            const uint32_t so = r * 144 + c * 16;
            const size_t g = (size_t)(row_off + r) * QKV_COLS + c * 8;
            cpa16(su32(dstbase + so), src + g);
        }
    };

    // ---- stage Q, pull fragments ----
    loadTile(qbh, dsm, q0);
    CP_COMMIT(); CP_WAIT(0); __syncthreads();

    uint32_t qh[4][4];
#pragma unroll
    for (int kc = 0; kc < 4; kc++) {
        const int rw = wid * 16 + (lane & 15);
        const int cl = kc * 16 + ((lane >> 4) << 3);
        ldsm4(qh[kc], su32(&Kh[rw * AST + cl]));
    }
    __syncthreads();

    loadTile(kbh, dsm, 0);
    loadTile(vbh, dsm + AARR, 0);
    CP_COMMIT(); CP_WAIT(0); __syncthreads();

    float oacc[8][4];
#pragma unroll
    for (int nt = 0; nt < 8; nt++)
#pragma unroll
        for (int i = 0; i < 4; i++) oacc[nt][i] = 0.f;
    // running max in base-2 logit units, running sum
    float mr0 = -1e30f, mr1 = -1e30f, lr0 = 0.f, lr1 = 0.f;

    for (int kt = 0; kt < 16; kt++) {
        const int vs = kt & 1;

        // ---- S = Q K^T ----
        float sacc[16][4];
#pragma unroll
        for (int nt = 0; nt < 16; nt++)
#pragma unroll
            for (int i = 0; i < 4; i++) sacc[nt][i] = 0.f;

#pragma unroll
        for (int np = 0; np < 8; np++) {
#pragma unroll
            for (int kc = 0; kc < 4; kc++) {
                uint32_t bh[4];
                const int rw = np * 16 + (lane & 15);
                const int cl = kc * 16 + ((lane >> 4) << 3);
                ldsm4(bh, su32(&Kh[rw * AST + cl]));
                mmaf16(sacc[np * 2],     qh[kc], bh[0], bh[2]);
                mmaf16(sacc[np * 2 + 1], qh[kc], bh[1], bh[3]);
            }
        }
        __syncthreads();                  // all warps done reading Kh
        if (kt < 15) {                    // prefetch next K and V
            loadTile(kbh, dsm, (kt + 1) * 128);
            loadTile(vbh, dsm + AARR + (vs ^ 1) * AARR, (kt + 1) * 128);
            CP_COMMIT();
        }

        // ---- online softmax (base-2 units: logit = sacc * C2) ----
        float tm0 = -1e30f, tm1 = -1e30f;
#pragma unroll
        for (int nt = 0; nt < 16; nt++) {
            tm0 = fmaxf(tm0, fmaxf(sacc[nt][0], sacc[nt][1]));
            tm1 = fmaxf(tm1, fmaxf(sacc[nt][2], sacc[nt][3]));
        }
        tm0 = fmaxf(tm0, __shfl_xor_sync(0xffffffffu, tm0, 1));
        tm0 = fmaxf(tm0, __shfl_xor_sync(0xffffffffu, tm0, 2));
        tm1 = fmaxf(tm1, __shfl_xor_sync(0xffffffffu, tm1, 1));
        tm1 = fmaxf(tm1, __shfl_xor_sync(0xffffffffu, tm1, 2));

        const float nm0 = fmaxf(mr0, tm0 * C2);
        const float nm1 = fmaxf(mr1, tm1 * C2);
        const float al0 = ex2(mr0 - nm0);
        const float al1 = ex2(mr1 - nm1);
        mr0 = nm0; mr1 = nm1;
#pragma unroll
        for (int nt = 0; nt < 8; nt++) {
            oacc[nt][0] *= al0; oacc[nt][1] *= al0;
            oacc[nt][2] *= al1; oacc[nt][3] *= al1;
        }

        float rs0 = 0.f, rs1 = 0.f;
        uint32_t php[8][4];
#pragma unroll
        for (int j = 0; j < 8; j++) {
            const float p00 = ex2(fmaf(sacc[2 * j][0],     C2, -nm0));
            const float p01 = ex2(fmaf(sacc[2 * j][1],     C2, -nm0));
            const float p10 = ex2(fmaf(sacc[2 * j][2],     C2, -nm1));
            const float p11 = ex2(fmaf(sacc[2 * j][3],     C2, -nm1));
            const float r00 = ex2(fmaf(sacc[2 * j + 1][0], C2, -nm0));
            const float r01 = ex2(fmaf(sacc[2 * j + 1][1], C2, -nm0));
            const float r10 = ex2(fmaf(sacc[2 * j + 1][2], C2, -nm1));
            const float r11 = ex2(fmaf(sacc[2 * j + 1][3], C2, -nm1));
            rs0 += (p00 + p01) + (r00 + r01);
            rs1 += (p10 + p11) + (r10 + r11);
            php[j][0] = pkh(p00, p01);
            php[j][1] = pkh(p10, p11);
            php[j][2] = pkh(r00, r01);
            php[j][3] = pkh(r10, r11);
        }
        rs0 += __shfl_xor_sync(0xffffffffu, rs0, 1);
        rs0 += __shfl_xor_sync(0xffffffffu, rs0, 2);
        rs1 += __shfl_xor_sync(0xffffffffu, rs1, 1);
        rs1 += __shfl_xor_sync(0xffffffffu, rs1, 2);
        lr0 = lr0 * al0 + rs0;
        lr1 = lr1 * al1 + rs1;

        // ---- O += P V ----
        const __half* Vh = (const __half*)(dsm + AARR + vs * AARR);
#pragma unroll
        for (int j = 0; j < 8; j++) {
#pragma unroll
            for (int dp = 0; dp < 4; dp++) {
                uint32_t vhf[4];
                const int rw = j * 16 + (lane & 7) + ((lane >> 3) & 1) * 8;
                const int cl = dp * 16 + ((lane >> 4) << 3);
                ldsm4t(vhf, su32(&Vh[rw * AST + cl]));
                mmaf16(oacc[dp * 2],     php[j], vhf[0], vhf[1]);
                mmaf16(oacc[dp * 2 + 1], php[j], vhf[2], vhf[3]);
            }
        }

        if (kt < 15) { CP_WAIT(0); __syncthreads(); }
    }

    // ---- epilogue: normalize, store fp16 ----
    const float inv0 = 1.f / lr0, inv1 = 1.f / lr1;
    const int g = lane >> 2, tq = lane & 3;
    const size_t r0o = (size_t)(b * T_ + q0 + wid * 16 + g);
#pragma unroll
    for (int nt = 0; nt < 8; nt++) {
        const int col = h * DH_ + nt * 8 + tq * 2;
        *(uint32_t*)&attnh[r0o * D_ + col] =
            pkh(oacc[nt][0] * inv0, oacc[nt][1] * inv0);
        *(uint32_t*)&attnh[(r0o + 8) * D_ + col] =
            pkh(oacc[nt][2] * inv1, oacc[nt][3] * inv1);
    }
}

// ---------------------------------------------------------------------------
// kernel_launch
// ---------------------------------------------------------------------------
extern "C" void kernel_launch(void* const* d_in, const int* in_sizes, int n_in,
                              void* d_out, int out_size)
{
    const float* x     = (const float*)d_in[0];
    const float* w_qkv = (const float*)d_in[1];
    const float* b_qkv = (const float*)d_in[2];
    const float* w_out = (const float*)d_in[3];
    const float* b_out = (const float*)d_in[4];
    float* out = (float*)d_out;

    __half *xh, *wqh, *woh, *qh, *ah;
    cudaGetSymbolAddress((void**)&xh,  g_x_h);
    cudaGetSymbolAddress((void**)&wqh, g_wqkv_h);
    cudaGetSymbolAddress((void**)&woh, g_wout_h);
    cudaGetSymbolAddress((void**)&qh,  g_qkv_h);
    cudaGetSymbolAddress((void**)&ah,  g_attn_h);

    // 0) round inputs to fp16
    presingle<<<1024, 256>>>(x,     xh,  NTOK * D_ / 4);
    presingle<<<1024, 256>>>(w_qkv, wqh, QKV_COLS * D_ / 4);
    presingle<<<512,  256>>>(w_out, woh, D_ * D_ / 4);

    const int gsmem = 2 * GSTAGE;  // 40960
    cudaFuncSetAttribute(gemm_f16<true>,
                         cudaFuncAttributeMaxDynamicSharedMemorySize, gsmem);
    cudaFuncSetAttribute(gemm_f16<false>,
                         cudaFuncAttributeMaxDynamicSharedMemorySize, gsmem);

    // 1) QKV projection -> fp16
    {
        dim3 grid(QKV_COLS / 128, NTOK / 128);
        gemm_f16<true><<<grid, 256, gsmem>>>(xh, wqh, b_qkv,
                                             nullptr, qh, QKV_COLS, D_);
    }

    // 2) Flash attention -> fp16
    {
        const int asmem = 3 * AARR;  // 55296
        cudaFuncSetAttribute(attn_f16,
                             cudaFuncAttributeMaxDynamicSharedMemorySize, asmem);
        dim3 grid(T_ / 128, B_ * H_);
        attn_f16<<<grid, 256, asmem>>>(qh, ah);
    }

    // 3) Output projection -> fp32
    {
        dim3 grid(D_ / 128, NTOK / 128);
        gemm_f16<false><<<grid, 256, gsmem>>>(ah, woh, b_out,
                                              out, nullptr, D_, D_);
    }
}

// round 7
// speedup vs baseline: 7.7522x; 1.0358x over previous
#include <cuda_runtime.h>
#include <cuda_fp16.h>
#include <math.h>
#include <stdint.h>

#define B_   4
#define T_   2048
#define D_   1024
#define H_   16
#define DH_  64
#define NTOK (B_ * T_)          // 8192
#define QKV_COLS (3 * D_)       // 3072

// ---------------------------------------------------------------------------
// fp16 global scratch (allocation-free rule: __device__ globals)
// ---------------------------------------------------------------------------
__device__ __half g_x_h[(size_t)NTOK * D_];
__device__ __half g_wqkv_h[(size_t)QKV_COLS * D_];
__device__ __half g_wout_h[(size_t)D_ * D_];
__device__ __half g_qkv_h[(size_t)NTOK * QKV_COLS];
__device__ __half g_attn_h[(size_t)NTOK * D_];

// ---------------------------------------------------------------------------
// helpers
// ---------------------------------------------------------------------------
__device__ __forceinline__ uint32_t su32(const void* p) {
    return (uint32_t)__cvta_generic_to_shared(p);
}
__device__ __forceinline__ void ldsm4(uint32_t* r, uint32_t a) {
    asm volatile("ldmatrix.sync.aligned.m8n8.x4.shared.b16 {%0,%1,%2,%3}, [%4];"
        : "=r"(r[0]), "=r"(r[1]), "=r"(r[2]), "=r"(r[3]) : "r"(a));
}
__device__ __forceinline__ void ldsm4t(uint32_t* r, uint32_t a) {
    asm volatile("ldmatrix.sync.aligned.m8n8.x4.trans.shared.b16 {%0,%1,%2,%3}, [%4];"
        : "=r"(r[0]), "=r"(r[1]), "=r"(r[2]), "=r"(r[3]) : "r"(a));
}
__device__ __forceinline__ void mmaf16(float* c, const uint32_t* a,
                                       uint32_t b0, uint32_t b1) {
    asm volatile(
        "mma.sync.aligned.m16n8k16.row.col.f32.f16.f16.f32 "
        "{%0,%1,%2,%3},{%4,%5,%6,%7},{%8,%9},{%0,%1,%2,%3};"
        : "+f"(c[0]), "+f"(c[1]), "+f"(c[2]), "+f"(c[3])
        : "r"(a[0]), "r"(a[1]), "r"(a[2]), "r"(a[3]), "r"(b0), "r"(b1));
}
__device__ __forceinline__ uint32_t pkh(float x, float y) {
    __half2 t = __floats2half2_rn(x, y);
    return *reinterpret_cast<uint32_t*>(&t);
}
__device__ __forceinline__ float ex2(float x) {
    float r;
    asm("ex2.approx.f32 %0, %1;" : "=f"(r) : "f"(x));
    return r;
}
__device__ __forceinline__ void cpa16(uint32_t s, const void* g) {
    asm volatile("cp.async.cg.shared.global [%0], [%1], 16;" :: "r"(s), "l"(g));
}
#define CP_COMMIT() asm volatile("cp.async.commit_group;" ::: "memory")
#define CP_WAIT(n)  asm volatile("cp.async.wait_group %0;" :: "n"(n) : "memory")

// ---------------------------------------------------------------------------
// presingle: fp32 -> fp16
// ---------------------------------------------------------------------------
__global__ void presingle(const float* __restrict__ in, __half* __restrict__ hi, int n4)
{
    int i = blockIdx.x * blockDim.x + threadIdx.x;
    const int stride = gridDim.x * blockDim.x;
    for (; i < n4; i += stride) {
        float4 v = ((const float4*)in)[i];
        ((uint2*)hi)[i] = make_uint2(pkh(v.x, v.y), pkh(v.z, v.w));
    }
}

// ---------------------------------------------------------------------------
// fp16 GEMM: C[M,Ntot] = A * Bw^T + bias
// BM=BN=128, BK=32, 256 threads (8 warps 4x2, warp tile 32x64).
// 4-stage cp.async pipeline (1 sync/iter), B-fragment double buffering.
// ---------------------------------------------------------------------------
#define GST 40                       // smem row stride in fp16 (80 bytes)
#define GARR (128 * GST * 2)         // 10240 bytes per array
#define GSTAGE (2 * GARR)            // 20480 bytes per stage
#define NSTG 4

template<bool WRITE_HALF>
__global__ __launch_bounds__(256, 2)
void gemm_f16(const __half* __restrict__ Ahg, const __half* __restrict__ Bhg,
              const float* __restrict__ bias,
              float* __restrict__ Cf, __half* __restrict__ Ch, int Ntot, int K)
{
    extern __shared__ char dsm[];

    const int tid = threadIdx.x, lane = tid & 31, wid = tid >> 5;
    const int wm = wid & 3, wn = wid >> 2;
    const int row0 = blockIdx.y * 128, col0 = blockIdx.x * 128;

    float acc[2][8][4];
#pragma unroll
    for (int mt = 0; mt < 2; mt++)
#pragma unroll
        for (int nt = 0; nt < 8; nt++)
#pragma unroll
            for (int i = 0; i < 4; i++) acc[mt][nt][i] = 0.f;

    auto prefetch = [&](int it) {
        char* base = dsm + (it & (NSTG - 1)) * GSTAGE;
#pragma unroll
        for (int i = 0; i < 2; i++) {
            const int id = tid + i * 256;        // 0..511
            const int r = id >> 2, c = id & 3;
            const uint32_t so = r * 80 + c * 16;
            cpa16(su32(base + so),        Ahg + (size_t)(row0 + r) * K + it * 32 + c * 8);
            cpa16(su32(base + GARR + so), Bhg + (size_t)(col0 + r) * K + it * 32 + c * 8);
        }
    };

    const int nit = K / 32;
#pragma unroll
    for (int it = 0; it < NSTG - 1; it++) { prefetch(it); CP_COMMIT(); }

    const int la = (lane & 15) * GST + ((lane >> 4) << 3);

    for (int it = 0; it < nit; it++) {
        CP_WAIT(NSTG - 2);
        __syncthreads();
        // refill the slot freed at the end of last iteration
        if (it + NSTG - 1 < nit) prefetch(it + NSTG - 1);
        CP_COMMIT();

        const __half* sA = (const __half*)(dsm + (it & (NSTG - 1)) * GSTAGE);
        const __half* sB = (const __half*)(dsm + (it & (NSTG - 1)) * GSTAGE + GARR);
        const uint32_t aw = su32(sA + wm * 32 * GST + la);
        const uint32_t bw = su32(sB + wn * 64 * GST + la);

#pragma unroll
        for (int kk = 0; kk < 2; kk++) {
            const uint32_t co = kk * 32;         // 16 halfs = 32 bytes
            uint32_t ah[2][4];
            ldsm4(ah[0], aw + co);
            ldsm4(ah[1], aw + 16 * GST * 2 + co);
            uint32_t bb[2][4];
            ldsm4(bb[0], bw + co);
#pragma unroll
            for (int np = 0; np < 4; np++) {
                const int cur = np & 1;
                if (np < 3)
                    ldsm4(bb[cur ^ 1], bw + (np + 1) * 16 * GST * 2 + co);
#pragma unroll
                for (int mt = 0; mt < 2; mt++) {
                    mmaf16(acc[mt][np * 2],     ah[mt], bb[cur][0], bb[cur][2]);
                    mmaf16(acc[mt][np * 2 + 1], ah[mt], bb[cur][1], bb[cur][3]);
                }
            }
        }
    }

    // epilogue
    const int g = lane >> 2, tq = lane & 3;
#pragma unroll
    for (int mt = 0; mt < 2; mt++) {
        const int r = row0 + wm * 32 + mt * 16 + g;
#pragma unroll
        for (int nt = 0; nt < 8; nt++) {
            const int c = col0 + wn * 64 + nt * 8 + tq * 2;
            float2 bi = *(const float2*)(bias + c);
            const float f0 = acc[mt][nt][0] + bi.x, f1 = acc[mt][nt][1] + bi.y;
            const float f2 = acc[mt][nt][2] + bi.x, f3 = acc[mt][nt][3] + bi.y;
            if (WRITE_HALF) {
                *(uint32_t*)&Ch[(size_t)r * Ntot + c]       = pkh(f0, f1);
                *(uint32_t*)&Ch[(size_t)(r + 8) * Ntot + c] = pkh(f2, f3);
            } else {
                *(float2*)(Cf + (size_t)r * Ntot + c)       = make_float2(f0, f1);
                *(float2*)(Cf + (size_t)(r + 8) * Ntot + c) = make_float2(f2, f3);
            }
        }
    }
}

// ---------------------------------------------------------------------------
// Flash attention, fp16, base-2 softmax, fragment-pipelined MMA loops.
// 256 threads (8 warps), 128 q-rows per block, one (b,h).
// smem: Kh [128][72] + Vh x2 stages = 54 KB -> 2 CTAs/SM.
// ---------------------------------------------------------------------------
#define AST 72
#define AARR (128 * AST * 2)   // 18432 bytes per array
#define C2   0.1803368801f     // (1/sqrt(64)) * log2(e)

__global__ __launch_bounds__(256, 2)
void attn_f16(const __half* __restrict__ qkvh, __half* __restrict__ attnh)
{
    extern __shared__ char dsm[];
    __half* Kh = (__half*)dsm;

    const int tid = threadIdx.x, lane = tid & 31, wid = tid >> 5;
    const int b = blockIdx.y >> 4, h = blockIdx.y & 15;
    const int q0 = blockIdx.x * 128;

    const size_t hb = (size_t)b * T_ * QKV_COLS + h * DH_;
    const __half* qbh = qkvh + hb;
    const __half* kbh = qbh + D_;
    const __half* vbh = qbh + 2 * D_;

    auto loadTile = [&](const __half* src, char* dstbase, int row_off) {
#pragma unroll
        for (int i = 0; i < 4; i++) {
            const int id = tid + i * 256;
            const int r = id >> 3, c = id & 7;
            const uint32_t so = r * 144 + c * 16;
            const size_t g = (size_t)(row_off + r) * QKV_COLS + c * 8;
            cpa16(su32(dstbase + so), src + g);
        }
    };

    // ---- stage Q, pull fragments ----
    loadTile(qbh, dsm, q0);
    CP_COMMIT(); CP_WAIT(0); __syncthreads();

    uint32_t qh[4][4];
#pragma unroll
    for (int kc = 0; kc < 4; kc++) {
        const int rw = wid * 16 + (lane & 15);
        const int cl = kc * 16 + ((lane >> 4) << 3);
        ldsm4(qh[kc], su32(&Kh[rw * AST + cl]));
    }
    __syncthreads();

    loadTile(kbh, dsm, 0);
    loadTile(vbh, dsm + AARR, 0);
    CP_COMMIT(); CP_WAIT(0); __syncthreads();

    float oacc[8][4];
#pragma unroll
    for (int nt = 0; nt < 8; nt++)
#pragma unroll
        for (int i = 0; i < 4; i++) oacc[nt][i] = 0.f;
    float mr0 = -1e30f, mr1 = -1e30f, lr0 = 0.f, lr1 = 0.f;

    // precomputed lane offsets
    const uint32_t kla = (lane & 15) * AST * 2 + ((lane >> 4) << 3) * 2;
    const uint32_t vla = ((lane & 7) + ((lane >> 3) & 1) * 8) * AST * 2 +
                         ((lane >> 4) << 3) * 2;

    for (int kt = 0; kt < 16; kt++) {
        const int vs = kt & 1;

        // ---- S = Q K^T  (32 LDSM / 64 MMA, frag double-buffered) ----
        float sacc[16][4];
#pragma unroll
        for (int nt = 0; nt < 16; nt++)
#pragma unroll
            for (int i = 0; i < 4; i++) sacc[nt][i] = 0.f;

        {
            const uint32_t kb0 = su32(Kh) + kla;
            uint32_t kb[2][4];
            ldsm4(kb[0], kb0);     // idx 0: np=0, kc=0
#pragma unroll
            for (int idx = 0; idx < 32; idx++) {
                const int np = idx >> 2, kc = idx & 3;
                const int cur = idx & 1;
                if (idx < 31) {
                    const int np1 = (idx + 1) >> 2, kc1 = (idx + 1) & 3;
                    ldsm4(kb[cur ^ 1], kb0 + np1 * 16 * AST * 2 + kc1 * 32);
                }
                mmaf16(sacc[np * 2],     qh[kc], kb[cur][0], kb[cur][2]);
                mmaf16(sacc[np * 2 + 1], qh[kc], kb[cur][1], kb[cur][3]);
            }
        }
        __syncthreads();                  // all warps done reading Kh
        if (kt < 15) {                    // prefetch next K and V
            loadTile(kbh, dsm, (kt + 1) * 128);
            loadTile(vbh, dsm + AARR + (vs ^ 1) * AARR, (kt + 1) * 128);
            CP_COMMIT();
        }

        // ---- online softmax (base-2 units) ----
        float tm0 = -1e30f, tm1 = -1e30f;
#pragma unroll
        for (int nt = 0; nt < 16; nt++) {
            tm0 = fmaxf(tm0, fmaxf(sacc[nt][0], sacc[nt][1]));
            tm1 = fmaxf(tm1, fmaxf(sacc[nt][2], sacc[nt][3]));
        }
        tm0 = fmaxf(tm0, __shfl_xor_sync(0xffffffffu, tm0, 1));
        tm0 = fmaxf(tm0, __shfl_xor_sync(0xffffffffu, tm0, 2));
        tm1 = fmaxf(tm1, __shfl_xor_sync(0xffffffffu, tm1, 1));
        tm1 = fmaxf(tm1, __shfl_xor_sync(0xffffffffu, tm1, 2));

        const float nm0 = fmaxf(mr0, tm0 * C2);
        const float nm1 = fmaxf(mr1, tm1 * C2);
        const float al0 = ex2(mr0 - nm0);
        const float al1 = ex2(mr1 - nm1);
        mr0 = nm0; mr1 = nm1;
#pragma unroll
        for (int nt = 0; nt < 8; nt++) {
            oacc[nt][0] *= al0; oacc[nt][1] *= al0;
            oacc[nt][2] *= al1; oacc[nt][3] *= al1;
        }

        float rs0 = 0.f, rs1 = 0.f;
        uint32_t php[8][4];
#pragma unroll
        for (int j = 0; j < 8; j++) {
            const float p00 = ex2(fmaf(sacc[2 * j][0],     C2, -nm0));
            const float p01 = ex2(fmaf(sacc[2 * j][1],     C2, -nm0));
            const float p10 = ex2(fmaf(sacc[2 * j][2],     C2, -nm1));
            const float p11 = ex2(fmaf(sacc[2 * j][3],     C2, -nm1));
            const float r00 = ex2(fmaf(sacc[2 * j + 1][0], C2, -nm0));
            const float r01 = ex2(fmaf(sacc[2 * j + 1][1], C2, -nm0));
            const float r10 = ex2(fmaf(sacc[2 * j + 1][2], C2, -nm1));
            const float r11 = ex2(fmaf(sacc[2 * j + 1][3], C2, -nm1));
            rs0 += (p00 + p01) + (r00 + r01);
            rs1 += (p10 + p11) + (r10 + r11);
            php[j][0] = pkh(p00, p01);
            php[j][1] = pkh(p10, p11);
            php[j][2] = pkh(r00, r01);
            php[j][3] = pkh(r10, r11);
        }
        rs0 += __shfl_xor_sync(0xffffffffu, rs0, 1);
        rs0 += __shfl_xor_sync(0xffffffffu, rs0, 2);
        rs1 += __shfl_xor_sync(0xffffffffu, rs1, 1);
        rs1 += __shfl_xor_sync(0xffffffffu, rs1, 2);
        lr0 = lr0 * al0 + rs0;
        lr1 = lr1 * al1 + rs1;

        // ---- O += P V  (32 LDSM.trans / 64 MMA, frag double-buffered) ----
        {
            const uint32_t vb0 = su32(dsm + AARR + vs * AARR) + vla;
            uint32_t vb[2][4];
            ldsm4t(vb[0], vb0);    // idx 0: j=0, dp=0
#pragma unroll
            for (int idx = 0; idx < 32; idx++) {
                const int j = idx >> 2, dp = idx & 3;
                const int cur = idx & 1;
                if (idx < 31) {
                    const int j1 = (idx + 1) >> 2, dp1 = (idx + 1) & 3;
                    ldsm4t(vb[cur ^ 1], vb0 + j1 * 16 * AST * 2 + dp1 * 32);
                }
                mmaf16(oacc[dp * 2],     php[j], vb[cur][0], vb[cur][1]);
                mmaf16(oacc[dp * 2 + 1], php[j], vb[cur][2], vb[cur][3]);
            }
        }

        if (kt < 15) { CP_WAIT(0); __syncthreads(); }
    }

    // ---- epilogue: normalize, store fp16 ----
    const float inv0 = 1.f / lr0, inv1 = 1.f / lr1;
    const int g = lane >> 2, tq = lane & 3;
    const size_t r0o = (size_t)(b * T_ + q0 + wid * 16 + g);
#pragma unroll
    for (int nt = 0; nt < 8; nt++) {
        const int col = h * DH_ + nt * 8 + tq * 2;
        *(uint32_t*)&attnh[r0o * D_ + col] =
            pkh(oacc[nt][0] * inv0, oacc[nt][1] * inv0);
        *(uint32_t*)&attnh[(r0o + 8) * D_ + col] =
            pkh(oacc[nt][2] * inv1, oacc[nt][3] * inv1);
    }
}

// ---------------------------------------------------------------------------
// kernel_launch
// ---------------------------------------------------------------------------
extern "C" void kernel_launch(void* const* d_in, const int* in_sizes, int n_in,
                              void* d_out, int out_size)
{
    const float* x     = (const float*)d_in[0];
    const float* w_qkv = (const float*)d_in[1];
    const float* b_qkv = (const float*)d_in[2];
    const float* w_out = (const float*)d_in[3];
    const float* b_out = (const float*)d_in[4];
    float* out = (float*)d_out;

    __half *xh, *wqh, *woh, *qh, *ah;
    cudaGetSymbolAddress((void**)&xh,  g_x_h);
    cudaGetSymbolAddress((void**)&wqh, g_wqkv_h);
    cudaGetSymbolAddress((void**)&woh, g_wout_h);
    cudaGetSymbolAddress((void**)&qh,  g_qkv_h);
    cudaGetSymbolAddress((void**)&ah,  g_attn_h);

    // 0) round inputs to fp16
    presingle<<<1024, 256>>>(x,     xh,  NTOK * D_ / 4);
    presingle<<<1024, 256>>>(w_qkv, wqh, QKV_COLS * D_ / 4);
    presingle<<<512,  256>>>(w_out, woh, D_ * D_ / 4);

    const int gsmem = NSTG * GSTAGE;  // 81920
    cudaFuncSetAttribute(gemm_f16<true>,
                         cudaFuncAttributeMaxDynamicSharedMemorySize, gsmem);
    cudaFuncSetAttribute(gemm_f16<false>,
                         cudaFuncAttributeMaxDynamicSharedMemorySize, gsmem);

    // 1) QKV projection -> fp16
    {
        dim3 grid(QKV_COLS / 128, NTOK / 128);
        gemm_f16<true><<<grid, 256, gsmem>>>(xh, wqh, b_qkv,
                                             nullptr, qh, QKV_COLS, D_);
    }

    // 2) Flash attention -> fp16
    {
        const int asmem = 3 * AARR;  // 55296
        cudaFuncSetAttribute(attn_f16,
                             cudaFuncAttributeMaxDynamicSharedMemorySize, asmem);
        dim3 grid(T_ / 128, B_ * H_);
        attn_f16<<<grid, 256, asmem>>>(qh, ah);
    }

    // 3) Output projection -> fp32
    {
        dim3 grid(D_ / 128, NTOK / 128);
        gemm_f16<false><<<grid, 256, gsmem>>>(ah, woh, b_out,
                                              out, nullptr, D_, D_);
    }
}